// round 1
// baseline (speedup 1.0000x reference)
#include <cuda_runtime.h>

#define BB 4
#define TT 512
#define NKV 512
#define DD 1024
#define EE 1024
#define HH 16
#define HD 64
#define BTD (BB*TT*DD)   // 2097152

// ---------------- scratch (static device memory; no allocation) ----------------
__device__ float g_se[BB*EE];
__device__ float g_eo[4][BB][2*DD];       // 0..2: branches, 3: xf
__device__ float g_h [4*BTD];             // modulated LN outputs (x1,x2,x3,xf)
__device__ float g_q [3*BTD];             // Q per branch
__device__ float g_k [BTD];
__device__ float g_v [BTD];
__device__ float g_ao[3*BTD];             // attention outputs per branch

// ---------------- silu ----------------
__global__ void silu_k(const float* __restrict__ emb) {
    int i = blockIdx.x * 256 + threadIdx.x;
    if (i < BB*EE) {
        float x = emb[i];
        g_se[i] = x / (1.0f + expf(-x));
    }
}

// ---------------- adaln: eo[m][b][:] = se[b] @ W_m + b_m  (4 mats) ----------------
__global__ void adaln_k(const float* __restrict__ aw, const float* __restrict__ ab,
                        const float* __restrict__ xw, const float* __restrict__ xb) {
    int m = blockIdx.x;                       // 0..3
    int o = blockIdx.y * 256 + threadIdx.x;   // 0..2047
    const float* Wm = (m < 3) ? aw + (size_t)m * EE * 2 * DD : xw;
    const float* Bm = (m < 3) ? ab + (size_t)m * 2 * DD      : xb;

    __shared__ float s[BB*EE];
    for (int i = threadIdx.x; i < BB*EE; i += 256) s[i] = g_se[i];
    __syncthreads();

    float acc[BB] = {0.f, 0.f, 0.f, 0.f};
    for (int e = 0; e < EE; e++) {
        float w = Wm[(size_t)e * 2 * DD + o];
        #pragma unroll
        for (int b = 0; b < BB; b++) acc[b] += s[b*EE + e] * w;
    }
    float bias = Bm[o];
    #pragma unroll
    for (int b = 0; b < BB; b++) g_eo[m][b][o] = acc[b] + bias;
}

// ---------------- LN + modulate: h = ln(x)*(1+scale) + shift ----------------
__global__ void ln_mod_k(const float* __restrict__ x1, const float* __restrict__ x2,
                         const float* __restrict__ x3, const float* __restrict__ xf) {
    int gr = blockIdx.x;          // 0..8191
    int t  = gr >> 11;            // tensor 0..3
    int r  = gr & 2047;           // row within tensor (b*512 + row)
    int b  = r >> 9;

    const float* xp;
    switch (t) { case 0: xp = x1; break; case 1: xp = x2; break;
                 case 2: xp = x3; break; default: xp = xf; }
    xp += (size_t)r * DD;

    float v[4]; float s = 0.f, q = 0.f;
    #pragma unroll
    for (int i = 0; i < 4; i++) {
        v[i] = xp[threadIdx.x + 256*i];
        s += v[i]; q += v[i]*v[i];
    }
    #pragma unroll
    for (int off = 16; off > 0; off >>= 1) {
        s += __shfl_down_sync(0xffffffffu, s, off);
        q += __shfl_down_sync(0xffffffffu, q, off);
    }
    __shared__ float sh1[8], sh2[8];
    if ((threadIdx.x & 31) == 0) { sh1[threadIdx.x >> 5] = s; sh2[threadIdx.x >> 5] = q; }
    __syncthreads();
    __shared__ float mu_s, rstd_s;
    if (threadIdx.x == 0) {
        float S = 0.f, Q = 0.f;
        #pragma unroll
        for (int i = 0; i < 8; i++) { S += sh1[i]; Q += sh2[i]; }
        float mu  = S / (float)DD;
        float var = Q / (float)DD - mu*mu;
        mu_s = mu; rstd_s = rsqrtf(var + 1e-6f);
    }
    __syncthreads();
    float mu = mu_s, rstd = rstd_s;
    const float* eo = g_eo[t][b];
    float* hp = &g_h[(size_t)t*BTD + (size_t)r*DD];
    #pragma unroll
    for (int i = 0; i < 4; i++) {
        int d = threadIdx.x + 256*i;
        hp[d] = (v[i] - mu) * rstd * (1.0f + eo[d]) + eo[DD + d];
    }
}

// ---------------- tiled SGEMM with bias: C[M,N] = A[M,K] @ W[K,N] + bias ----------------
__global__ void __launch_bounds__(256)
sgemm_bias(const float* __restrict__ A, const float* __restrict__ W,
           const float* __restrict__ bias, float* __restrict__ C,
           int M, int N, int K) {
    __shared__ float As[8][128];
    __shared__ float Bs[8][128];
    int brow = blockIdx.y * 128, bcol = blockIdx.x * 128;
    int tid = threadIdx.x;
    int tr = tid / 16, tc = tid % 16;

    float acc[8][8];
    #pragma unroll
    for (int i = 0; i < 8; i++)
        #pragma unroll
        for (int j = 0; j < 8; j++) acc[i][j] = 0.f;

    for (int k0 = 0; k0 < K; k0 += 8) {
        // A tile: 128 rows x 8 cols, load as float4 along K, store transposed
        {
            int r  = tid >> 1;
            int c4 = (tid & 1) * 4;
            float4 av = *(const float4*)&A[(size_t)(brow + r) * K + k0 + c4];
            As[c4+0][r] = av.x; As[c4+1][r] = av.y; As[c4+2][r] = av.z; As[c4+3][r] = av.w;
        }
        // B tile: 8 rows x 128 cols, coalesced
        #pragma unroll
        for (int i = tid; i < 1024; i += 256) {
            int c = i >> 7, n = i & 127;
            Bs[c][n] = W[(size_t)(k0 + c) * N + bcol + n];
        }
        __syncthreads();
        #pragma unroll
        for (int kk = 0; kk < 8; kk++) {
            float a[8], bv[8];
            #pragma unroll
            for (int i = 0; i < 8; i++) a[i]  = As[kk][tr*8 + i];
            #pragma unroll
            for (int j = 0; j < 8; j++) bv[j] = Bs[kk][tc*8 + j];
            #pragma unroll
            for (int i = 0; i < 8; i++)
                #pragma unroll
                for (int j = 0; j < 8; j++) acc[i][j] += a[i] * bv[j];
        }
        __syncthreads();
    }
    #pragma unroll
    for (int i = 0; i < 8; i++) {
        int row = brow + tr*8 + i;
        #pragma unroll
        for (int j = 0; j < 8; j++) {
            int col = bcol + tc*8 + j;
            C[(size_t)row * N + col] = acc[i][j] + bias[col];
        }
    }
}

// ---------------- flash-style attention, 1 thread = 1 query row ----------------
__global__ void __launch_bounds__(128)
attn_k(const unsigned char* __restrict__ mask) {
    int br = blockIdx.z >> 2;   // branch 0..2
    int b  = blockIdx.z & 3;
    int h  = blockIdx.y;
    int q  = blockIdx.x * 128 + threadIdx.x;

    const float* Qp = &g_q[(size_t)br*BTD + ((size_t)(b*TT + q))*DD + h*HD];
    float qv[HD];
    #pragma unroll
    for (int i = 0; i < HD; i++) qv[i] = Qp[i] * 0.125f;  // 1/sqrt(64)

    float O[HD];
    #pragma unroll
    for (int i = 0; i < HD; i++) O[i] = 0.f;
    float m = -1e30f, l = 0.f;

    __shared__ float Ks[32][HD];
    __shared__ float Vs[32][HD];
    __shared__ unsigned char ms[32];

    for (int kc = 0; kc < NKV; kc += 32) {
        __syncthreads();
        // cooperative load of K/V chunk (float4, coalesced)
        #pragma unroll
        for (int i = threadIdx.x; i < 32*16; i += 128) {
            int n = i >> 4, c = (i & 15) * 4;
            size_t base = ((size_t)(b*NKV + kc + n)) * DD + h*HD + c;
            *(float4*)&Ks[n][c] = *(const float4*)&g_k[base];
            *(float4*)&Vs[n][c] = *(const float4*)&g_v[base];
        }
        if (threadIdx.x < 32) ms[threadIdx.x] = mask[b*NKV + kc + threadIdx.x];
        __syncthreads();

        float s[32];
        float cmax = -1e30f;
        #pragma unroll
        for (int n = 0; n < 32; n++) {
            float acc = 0.f;
            #pragma unroll
            for (int i = 0; i < HD; i++) acc += qv[i] * Ks[n][i];
            if (ms[n]) acc = -1e30f;
            s[n] = acc;
            cmax = fmaxf(cmax, acc);
        }
        float mn = fmaxf(m, cmax);
        float f  = __expf(m - mn);
        float la = 0.f;
        #pragma unroll
        for (int n = 0; n < 32; n++) { float p = __expf(s[n] - mn); s[n] = p; la += p; }
        l = l * f + la;
        m = mn;
        #pragma unroll
        for (int i = 0; i < HD; i++) O[i] *= f;
        #pragma unroll
        for (int n = 0; n < 32; n++) {
            float p = s[n];
            #pragma unroll
            for (int i = 0; i < HD; i++) O[i] += p * Vs[n][i];
        }
    }
    float rl = (l > 0.f) ? 1.0f / l : 0.f;
    float* op = &g_ao[(size_t)br*BTD + ((size_t)(b*TT + q))*DD + h*HD];
    #pragma unroll
    for (int i = 0; i < HD; i++) op[i] = O[i] * rl;
}

// ---------------- launch ----------------
extern "C" void kernel_launch(void* const* d_in, const int* in_sizes, int n_in,
                              void* d_out, int out_size) {
    const float* x1        = (const float*)d_in[0];
    const float* x2        = (const float*)d_in[1];
    const float* x3        = (const float*)d_in[2];
    const float* xf        = (const float*)d_in[3];
    const float* emb       = (const float*)d_in[4];
    const unsigned char* mask = (const unsigned char*)d_in[5];
    const float* adaln_w   = (const float*)d_in[6];
    const float* adaln_b   = (const float*)d_in[7];
    const float* xf_adaln_w= (const float*)d_in[8];
    const float* xf_adaln_b= (const float*)d_in[9];
    const float* q_w       = (const float*)d_in[10];
    const float* q_b       = (const float*)d_in[11];
    const float* k_w       = (const float*)d_in[12];
    const float* k_b       = (const float*)d_in[13];
    const float* v_w       = (const float*)d_in[14];
    const float* v_b       = (const float*)d_in[15];
    const float* out_w     = (const float*)d_in[16];
    const float* out_b     = (const float*)d_in[17];
    float* out = (float*)d_out;

    float *hP, *qP, *kP, *vP, *aoP;
    cudaGetSymbolAddress((void**)&hP,  g_h);
    cudaGetSymbolAddress((void**)&qP,  g_q);
    cudaGetSymbolAddress((void**)&kP,  g_k);
    cudaGetSymbolAddress((void**)&vP,  g_v);
    cudaGetSymbolAddress((void**)&aoP, g_ao);

    silu_k<<<(BB*EE + 255)/256, 256>>>(emb);
    adaln_k<<<dim3(4, 8), 256>>>(adaln_w, adaln_b, xf_adaln_w, xf_adaln_b);
    ln_mod_k<<<4 * BB * TT, 256>>>(x1, x2, x3, xf);

    dim3 ggrid(DD/128, (BB*TT)/128);   // (8,16)
    for (int i = 0; i < 3; i++)
        sgemm_bias<<<ggrid, 256>>>(hP + (size_t)i*BTD, q_w + (size_t)i*DD*DD,
                                   q_b + i*DD, qP + (size_t)i*BTD,
                                   BB*TT, DD, DD);
    sgemm_bias<<<ggrid, 256>>>(hP + (size_t)3*BTD, k_w, k_b, kP, BB*NKV, DD, DD);
    sgemm_bias<<<ggrid, 256>>>(hP + (size_t)3*BTD, v_w, v_b, vP, BB*NKV, DD, DD);

    attn_k<<<dim3(TT/128, HH, 3*BB), 128>>>(mask);

    for (int i = 0; i < 3; i++)
        sgemm_bias<<<ggrid, 256>>>(aoP + (size_t)i*BTD, out_w + (size_t)i*DD*DD,
                                   out_b + i*DD, out + (size_t)i*BTD,
                                   BB*TT, DD, DD);
}

// round 2
// speedup vs baseline: 1.9412x; 1.9412x over previous
#include <cuda_runtime.h>
#include <cstdint>

#define BB 4
#define TT 512
#define NKV 512
#define DD 1024
#define EE 1024
#define HH 16
#define HD 64
#define BTD (BB*TT*DD)   // 2097152

// ---------------- scratch (static device memory; no allocation) ----------------
__device__ float g_se[BB*EE];
__device__ float g_eo[4][BB][2*DD];       // 0..2: branches, 3: xf
__device__ float g_h [4*BTD];             // modulated LN outputs (x1,x2,x3,xf)
__device__ float g_q [3*BTD];             // Q per branch
__device__ float g_k [BTD];
__device__ float g_v [BTD];
__device__ float g_ao[3*BTD];             // attention outputs per branch

// ---------------- silu ----------------
__global__ void silu_k(const float* __restrict__ emb) {
    int i = blockIdx.x * 256 + threadIdx.x;
    if (i < BB*EE) {
        float x = emb[i];
        g_se[i] = x / (1.0f + expf(-x));
    }
}

// ---------------- adaln: eo[m][b][:] = se[b] @ W_m + b_m  (4 mats) ----------------
// grid = 64 blocks (4 mats x 16 col-groups), 256 threads, split-K over E halves
__global__ void adaln_k(const float* __restrict__ aw, const float* __restrict__ ab,
                        const float* __restrict__ xw, const float* __restrict__ xb) {
    int m = blockIdx.x >> 4;
    int oc = (blockIdx.x & 15) << 7;
    int o  = oc + (threadIdx.x & 127);
    int half = threadIdx.x >> 7;
    const float* Wm = (m < 3) ? aw + (size_t)m * EE * 2 * DD : xw;
    const float* Bm = (m < 3) ? ab + (size_t)m * 2 * DD      : xb;

    __shared__ float s[BB*EE];
    for (int i = threadIdx.x; i < BB*EE; i += 256) s[i] = g_se[i];
    __syncthreads();

    float acc[BB] = {0.f, 0.f, 0.f, 0.f};
    int e0 = half * 512;
    for (int e = e0; e < e0 + 512; e++) {
        float w = Wm[(size_t)e * 2 * DD + o];
        #pragma unroll
        for (int b = 0; b < BB; b++) acc[b] += s[b*EE + e] * w;
    }
    __shared__ float red[128][4];
    if (half) {
        #pragma unroll
        for (int b = 0; b < BB; b++) red[threadIdx.x & 127][b] = acc[b];
    }
    __syncthreads();
    if (!half) {
        float bias = Bm[o];
        #pragma unroll
        for (int b = 0; b < BB; b++)
            g_eo[m][b][o] = acc[b] + red[threadIdx.x][b] + bias;
    }
}

// ---------------- LN + modulate: h = ln(x)*(1+scale) + shift ----------------
__global__ void ln_mod_k(const float* __restrict__ x1, const float* __restrict__ x2,
                         const float* __restrict__ x3, const float* __restrict__ xf) {
    int gr = blockIdx.x;          // 0..8191
    int t  = gr >> 11;            // tensor 0..3
    int r  = gr & 2047;           // row within tensor (b*512 + row)
    int b  = r >> 9;

    const float* xp;
    switch (t) { case 0: xp = x1; break; case 1: xp = x2; break;
                 case 2: xp = x3; break; default: xp = xf; }
    xp += (size_t)r * DD;

    float v[4]; float s = 0.f, q = 0.f;
    #pragma unroll
    for (int i = 0; i < 4; i++) {
        v[i] = xp[threadIdx.x + 256*i];
        s += v[i]; q += v[i]*v[i];
    }
    #pragma unroll
    for (int off = 16; off > 0; off >>= 1) {
        s += __shfl_down_sync(0xffffffffu, s, off);
        q += __shfl_down_sync(0xffffffffu, q, off);
    }
    __shared__ float sh1[8], sh2[8];
    if ((threadIdx.x & 31) == 0) { sh1[threadIdx.x >> 5] = s; sh2[threadIdx.x >> 5] = q; }
    __syncthreads();
    __shared__ float mu_s, rstd_s;
    if (threadIdx.x == 0) {
        float S = 0.f, Q = 0.f;
        #pragma unroll
        for (int i = 0; i < 8; i++) { S += sh1[i]; Q += sh2[i]; }
        float mu  = S / (float)DD;
        float var = Q / (float)DD - mu*mu;
        mu_s = mu; rstd_s = rsqrtf(var + 1e-6f);
    }
    __syncthreads();
    float mu = mu_s, rstd = rstd_s;
    const float* eo = g_eo[t][b];
    float* hp = &g_h[(size_t)t*BTD + (size_t)r*DD];
    #pragma unroll
    for (int i = 0; i < 4; i++) {
        int d = threadIdx.x + 256*i;
        hp[d] = (v[i] - mu) * rstd * (1.0f + eo[d]) + eo[DD + d];
    }
}

// ---------------- TF32 tensor-core GEMM with bias ----------------
// C[M,N] = A[M,K] @ W[K,N] + bias
// 128x128 CTA tile, BK=16, 4 warps of 64x64, double-buffered smem.
// A smem: [m][k], row padded to 20 words (conflict-free frag reads).
// B smem: [k][n], row padded to 136 words (conflict-free reads + STS.128 stores).

__device__ __forceinline__ float tf32r(float x) {
    uint32_t u;
    asm("cvt.rna.tf32.f32 %0, %1;" : "=r"(u) : "f"(x));
    return __uint_as_float(u);
}

__device__ __forceinline__ void mma_tf32(float c[4],
        uint32_t a0, uint32_t a1, uint32_t a2, uint32_t a3,
        uint32_t b0, uint32_t b1) {
    asm volatile("mma.sync.aligned.m16n8k8.row.col.f32.tf32.tf32.f32 "
        "{%0,%1,%2,%3}, {%4,%5,%6,%7}, {%8,%9}, {%0,%1,%2,%3};"
        : "+f"(c[0]), "+f"(c[1]), "+f"(c[2]), "+f"(c[3])
        : "r"(a0), "r"(a1), "r"(a2), "r"(a3), "r"(b0), "r"(b1));
}

#define PADA 20
#define PADB 136

__global__ void __launch_bounds__(128)
mma_gemm(const float* __restrict__ A, const float* __restrict__ W,
         const float* __restrict__ bias, float* __restrict__ C,
         int M, int N, int K) {
    __shared__ float As[2][128*PADA];
    __shared__ float Bs[2][16*PADB];

    const int tid  = threadIdx.x;
    const int lane = tid & 31, warp = tid >> 5;
    const int g = lane >> 2, tig = lane & 3;
    const int mo = (warp >> 1) << 6;     // warp m offset (0/64)
    const int no = (warp & 1) << 6;      // warp n offset (0/64)
    const int brow = blockIdx.y << 7, bcol = blockIdx.x << 7;

    const int ar = tid >> 2, af = tid & 3;   // A loader: rows ar+32*rr, float4 af
    const int bk = tid >> 3, bc = tid & 7;   // B loader: row bk, float4 cols bc+8j

    float acc[4][8][4];
    #pragma unroll
    for (int mt = 0; mt < 4; mt++)
        #pragma unroll
        for (int nt = 0; nt < 8; nt++)
            #pragma unroll
            for (int i = 0; i < 4; i++) acc[mt][nt][i] = 0.f;

    float4 la[4], lb[4];

    // prologue: load tile 0
    #pragma unroll
    for (int rr = 0; rr < 4; rr++)
        la[rr] = *(const float4*)&A[(size_t)(brow + ar + 32*rr) * K + af*4];
    #pragma unroll
    for (int j = 0; j < 4; j++)
        lb[j] = *(const float4*)&W[(size_t)bk * N + bcol + (bc + 8*j)*4];
    #pragma unroll
    for (int rr = 0; rr < 4; rr++) {
        float4 v = la[rr];
        float4 t = make_float4(tf32r(v.x), tf32r(v.y), tf32r(v.z), tf32r(v.w));
        *(float4*)&As[0][(ar + 32*rr)*PADA + af*4] = t;
    }
    #pragma unroll
    for (int j = 0; j < 4; j++) {
        float4 v = lb[j];
        float4 t = make_float4(tf32r(v.x), tf32r(v.y), tf32r(v.z), tf32r(v.w));
        *(float4*)&Bs[0][bk*PADB + (bc + 8*j)*4] = t;
    }
    __syncthreads();

    const int iters = K >> 4;
    for (int it = 0; it < iters; ++it) {
        // prefetch next tile into registers (latency hidden by compute)
        if (it + 1 < iters) {
            int k0 = (it + 1) << 4;
            #pragma unroll
            for (int rr = 0; rr < 4; rr++)
                la[rr] = *(const float4*)&A[(size_t)(brow + ar + 32*rr) * K + k0 + af*4];
            #pragma unroll
            for (int j = 0; j < 4; j++)
                lb[j] = *(const float4*)&W[(size_t)(k0 + bk) * N + bcol + (bc + 8*j)*4];
        }

        // compute current buffer
        const float* as = As[it & 1];
        const float* bs = Bs[it & 1];
        #pragma unroll
        for (int ks = 0; ks < 2; ks++) {
            const int kb = ks*8 + tig;
            uint32_t afr[4][4], bfr[8][2];
            #pragma unroll
            for (int mt = 0; mt < 4; mt++) {
                int r0 = mo + mt*16 + g;
                afr[mt][0] = __float_as_uint(as[ r0     *PADA + kb    ]);
                afr[mt][1] = __float_as_uint(as[(r0 + 8)*PADA + kb    ]);
                afr[mt][2] = __float_as_uint(as[ r0     *PADA + kb + 4]);
                afr[mt][3] = __float_as_uint(as[(r0 + 8)*PADA + kb + 4]);
            }
            #pragma unroll
            for (int nt = 0; nt < 8; nt++) {
                int n = no + nt*8 + g;
                bfr[nt][0] = __float_as_uint(bs[ kb     *PADB + n]);
                bfr[nt][1] = __float_as_uint(bs[(kb + 4)*PADB + n]);
            }
            #pragma unroll
            for (int mt = 0; mt < 4; mt++)
                #pragma unroll
                for (int nt = 0; nt < 8; nt++)
                    mma_tf32(acc[mt][nt], afr[mt][0], afr[mt][1], afr[mt][2], afr[mt][3],
                             bfr[nt][0], bfr[nt][1]);
        }

        // stage next tile into the other buffer
        if (it + 1 < iters) {
            int nb = (it + 1) & 1;
            #pragma unroll
            for (int rr = 0; rr < 4; rr++) {
                float4 v = la[rr];
                float4 t = make_float4(tf32r(v.x), tf32r(v.y), tf32r(v.z), tf32r(v.w));
                *(float4*)&As[nb][(ar + 32*rr)*PADA + af*4] = t;
            }
            #pragma unroll
            for (int j = 0; j < 4; j++) {
                float4 v = lb[j];
                float4 t = make_float4(tf32r(v.x), tf32r(v.y), tf32r(v.z), tf32r(v.w));
                *(float4*)&Bs[nb][bk*PADB + (bc + 8*j)*4] = t;
            }
        }
        __syncthreads();
    }

    // epilogue: bias add + store
    #pragma unroll
    for (int mt = 0; mt < 4; mt++) {
        int r0 = brow + mo + mt*16 + g;
        #pragma unroll
        for (int nt = 0; nt < 8; nt++) {
            int c = bcol + no + nt*8 + 2*tig;
            float b0 = bias[c], b1 = bias[c + 1];
            float2 v0 = make_float2(acc[mt][nt][0] + b0, acc[mt][nt][1] + b1);
            float2 v1 = make_float2(acc[mt][nt][2] + b0, acc[mt][nt][3] + b1);
            *(float2*)&C[(size_t)r0       * N + c] = v0;
            *(float2*)&C[(size_t)(r0 + 8) * N + c] = v1;
        }
    }
}

// ---------------- flash-style attention, 1 thread = 1 query row ----------------
__global__ void __launch_bounds__(128)
attn_k(const unsigned char* __restrict__ mask) {
    int br = blockIdx.z >> 2;   // branch 0..2
    int b  = blockIdx.z & 3;
    int h  = blockIdx.y;
    int q  = blockIdx.x * 128 + threadIdx.x;

    const float* Qp = &g_q[(size_t)br*BTD + ((size_t)(b*TT + q))*DD + h*HD];
    float qv[HD];
    #pragma unroll
    for (int i = 0; i < HD; i++) qv[i] = Qp[i] * 0.125f;  // 1/sqrt(64)

    float O[HD];
    #pragma unroll
    for (int i = 0; i < HD; i++) O[i] = 0.f;
    float m = -1e30f, l = 0.f;

    __shared__ float Ks[32][HD];
    __shared__ float Vs[32][HD];
    __shared__ unsigned char ms[32];

    for (int kc = 0; kc < NKV; kc += 32) {
        __syncthreads();
        #pragma unroll
        for (int i = threadIdx.x; i < 32*16; i += 128) {
            int n = i >> 4, c = (i & 15) * 4;
            size_t base = ((size_t)(b*NKV + kc + n)) * DD + h*HD + c;
            *(float4*)&Ks[n][c] = *(const float4*)&g_k[base];
            *(float4*)&Vs[n][c] = *(const float4*)&g_v[base];
        }
        if (threadIdx.x < 32) ms[threadIdx.x] = mask[b*NKV + kc + threadIdx.x];
        __syncthreads();

        float s[32];
        float cmax = -1e30f;
        #pragma unroll
        for (int n = 0; n < 32; n++) {
            float acc = 0.f;
            #pragma unroll
            for (int i = 0; i < HD; i++) acc += qv[i] * Ks[n][i];
            if (ms[n]) acc = -1e30f;
            s[n] = acc;
            cmax = fmaxf(cmax, acc);
        }
        float mn = fmaxf(m, cmax);
        float f  = __expf(m - mn);
        float la = 0.f;
        #pragma unroll
        for (int n = 0; n < 32; n++) { float p = __expf(s[n] - mn); s[n] = p; la += p; }
        l = l * f + la;
        m = mn;
        #pragma unroll
        for (int i = 0; i < HD; i++) O[i] *= f;
        #pragma unroll
        for (int n = 0; n < 32; n++) {
            float p = s[n];
            #pragma unroll
            for (int i = 0; i < HD; i++) O[i] += p * Vs[n][i];
        }
    }
    float rl = (l > 0.f) ? 1.0f / l : 0.f;
    float* op = &g_ao[(size_t)br*BTD + ((size_t)(b*TT + q))*DD + h*HD];
    #pragma unroll
    for (int i = 0; i < HD; i++) op[i] = O[i] * rl;
}

// ---------------- launch ----------------
extern "C" void kernel_launch(void* const* d_in, const int* in_sizes, int n_in,
                              void* d_out, int out_size) {
    const float* x1        = (const float*)d_in[0];
    const float* x2        = (const float*)d_in[1];
    const float* x3        = (const float*)d_in[2];
    const float* xf        = (const float*)d_in[3];
    const float* emb       = (const float*)d_in[4];
    const unsigned char* mask = (const unsigned char*)d_in[5];
    const float* adaln_w   = (const float*)d_in[6];
    const float* adaln_b   = (const float*)d_in[7];
    const float* xf_adaln_w= (const float*)d_in[8];
    const float* xf_adaln_b= (const float*)d_in[9];
    const float* q_w       = (const float*)d_in[10];
    const float* q_b       = (const float*)d_in[11];
    const float* k_w       = (const float*)d_in[12];
    const float* k_b       = (const float*)d_in[13];
    const float* v_w       = (const float*)d_in[14];
    const float* v_b       = (const float*)d_in[15];
    const float* out_w     = (const float*)d_in[16];
    const float* out_b     = (const float*)d_in[17];
    float* out = (float*)d_out;

    float *hP, *qP, *kP, *vP, *aoP;
    cudaGetSymbolAddress((void**)&hP,  g_h);
    cudaGetSymbolAddress((void**)&qP,  g_q);
    cudaGetSymbolAddress((void**)&kP,  g_k);
    cudaGetSymbolAddress((void**)&vP,  g_v);
    cudaGetSymbolAddress((void**)&aoP, g_ao);

    silu_k<<<(BB*EE + 255)/256, 256>>>(emb);
    adaln_k<<<64, 256>>>(adaln_w, adaln_b, xf_adaln_w, xf_adaln_b);
    ln_mod_k<<<4 * BB * TT, 256>>>(x1, x2, x3, xf);

    dim3 ggrid(DD/128, (BB*TT)/128);   // (8,16) = 128 CTAs
    for (int i = 0; i < 3; i++)
        mma_gemm<<<ggrid, 128>>>(hP + (size_t)i*BTD, q_w + (size_t)i*DD*DD,
                                 q_b + i*DD, qP + (size_t)i*BTD,
                                 BB*TT, DD, DD);
    mma_gemm<<<ggrid, 128>>>(hP + (size_t)3*BTD, k_w, k_b, kP, BB*NKV, DD, DD);
    mma_gemm<<<ggrid, 128>>>(hP + (size_t)3*BTD, v_w, v_b, vP, BB*NKV, DD, DD);

    attn_k<<<dim3(TT/128, HH, 3*BB), 128>>>(mask);

    for (int i = 0; i < 3; i++)
        mma_gemm<<<ggrid, 128>>>(aoP + (size_t)i*BTD, out_w + (size_t)i*DD*DD,
                                 out_b + i*DD, out + (size_t)i*BTD,
                                 BB*TT, DD, DD);
}

// round 3
// speedup vs baseline: 4.0569x; 2.0899x over previous
#include <cuda_runtime.h>
#include <cstdint>

#define BB 4
#define TT 512
#define NKV 512
#define DD 1024
#define EE 1024
#define HH 16
#define HD 64
#define BTD (BB*TT*DD)   // 2097152

// ---------------- scratch (static device memory; no allocation) ----------------
__device__ float g_se[BB*EE];
__device__ float g_eo[4][BB][2*DD];
__device__ float g_h [4*BTD];
__device__ float g_q [3*BTD];
__device__ float g_k [BTD];
__device__ float g_v [BTD];
__device__ float g_ao[3*BTD];

// ---------------- silu ----------------
__global__ void silu_k(const float* __restrict__ emb) {
    int i = blockIdx.x * 256 + threadIdx.x;
    if (i < BB*EE) {
        float x = emb[i];
        g_se[i] = x / (1.0f + expf(-x));
    }
}

// ---------------- adaln ----------------
__global__ void adaln_k(const float* __restrict__ aw, const float* __restrict__ ab,
                        const float* __restrict__ xw, const float* __restrict__ xb) {
    int m = blockIdx.x >> 4;
    int oc = (blockIdx.x & 15) << 7;
    int o  = oc + (threadIdx.x & 127);
    int half = threadIdx.x >> 7;
    const float* Wm = (m < 3) ? aw + (size_t)m * EE * 2 * DD : xw;
    const float* Bm = (m < 3) ? ab + (size_t)m * 2 * DD      : xb;

    __shared__ float s[BB*EE];
    for (int i = threadIdx.x; i < BB*EE; i += 256) s[i] = g_se[i];
    __syncthreads();

    float acc[BB] = {0.f, 0.f, 0.f, 0.f};
    int e0 = half * 512;
    for (int e = e0; e < e0 + 512; e++) {
        float w = Wm[(size_t)e * 2 * DD + o];
        #pragma unroll
        for (int b = 0; b < BB; b++) acc[b] += s[b*EE + e] * w;
    }
    __shared__ float red[128][4];
    if (half) {
        #pragma unroll
        for (int b = 0; b < BB; b++) red[threadIdx.x & 127][b] = acc[b];
    }
    __syncthreads();
    if (!half) {
        float bias = Bm[o];
        #pragma unroll
        for (int b = 0; b < BB; b++)
            g_eo[m][b][o] = acc[b] + red[threadIdx.x][b] + bias;
    }
}

// ---------------- LN + modulate ----------------
__global__ void ln_mod_k(const float* __restrict__ x1, const float* __restrict__ x2,
                         const float* __restrict__ x3, const float* __restrict__ xf) {
    int gr = blockIdx.x;
    int t  = gr >> 11;
    int r  = gr & 2047;
    int b  = r >> 9;

    const float* xp;
    switch (t) { case 0: xp = x1; break; case 1: xp = x2; break;
                 case 2: xp = x3; break; default: xp = xf; }
    xp += (size_t)r * DD;

    float v[4]; float s = 0.f, q = 0.f;
    #pragma unroll
    for (int i = 0; i < 4; i++) {
        v[i] = xp[threadIdx.x + 256*i];
        s += v[i]; q += v[i]*v[i];
    }
    #pragma unroll
    for (int off = 16; off > 0; off >>= 1) {
        s += __shfl_down_sync(0xffffffffu, s, off);
        q += __shfl_down_sync(0xffffffffu, q, off);
    }
    __shared__ float sh1[8], sh2[8];
    if ((threadIdx.x & 31) == 0) { sh1[threadIdx.x >> 5] = s; sh2[threadIdx.x >> 5] = q; }
    __syncthreads();
    __shared__ float mu_s, rstd_s;
    if (threadIdx.x == 0) {
        float S = 0.f, Q = 0.f;
        #pragma unroll
        for (int i = 0; i < 8; i++) { S += sh1[i]; Q += sh2[i]; }
        float mu  = S / (float)DD;
        float var = Q / (float)DD - mu*mu;
        mu_s = mu; rstd_s = rsqrtf(var + 1e-6f);
    }
    __syncthreads();
    float mu = mu_s, rstd = rstd_s;
    const float* eo = g_eo[t][b];
    float* hp = &g_h[(size_t)t*BTD + (size_t)r*DD];
    #pragma unroll
    for (int i = 0; i < 4; i++) {
        int d = threadIdx.x + 256*i;
        hp[d] = (v[i] - mu) * rstd * (1.0f + eo[d]) + eo[DD + d];
    }
}

// ---------------- TF32 helpers ----------------
__device__ __forceinline__ float tf32r(float x) {
    uint32_t u;
    asm("cvt.rna.tf32.f32 %0, %1;" : "=r"(u) : "f"(x));
    return __uint_as_float(u);
}

__device__ __forceinline__ void mma_tf32(float c[4],
        uint32_t a0, uint32_t a1, uint32_t a2, uint32_t a3,
        uint32_t b0, uint32_t b1) {
    asm volatile("mma.sync.aligned.m16n8k8.row.col.f32.tf32.tf32.f32 "
        "{%0,%1,%2,%3}, {%4,%5,%6,%7}, {%8,%9}, {%0,%1,%2,%3};"
        : "+f"(c[0]), "+f"(c[1]), "+f"(c[2]), "+f"(c[3])
        : "r"(a0), "r"(a1), "r"(a2), "r"(a3), "r"(b0), "r"(b1));
}

// ---------------- batched TF32 GEMM with bias ----------------
#define PADA 20
#define PADB 136
#define MAXZ 5

struct GemmBatch {
    const float* A[MAXZ];
    const float* W[MAXZ];
    const float* bias[MAXZ];
    float*       C[MAXZ];
};

__global__ void __launch_bounds__(128)
mma_gemm(GemmBatch gb, int M, int N, int K) {
    __shared__ float As[2][128*PADA];
    __shared__ float Bs[2][16*PADB];

    const int z = blockIdx.z;
    const float* __restrict__ A    = gb.A[z];
    const float* __restrict__ W    = gb.W[z];
    const float* __restrict__ bias = gb.bias[z];
    float* __restrict__ C          = gb.C[z];

    const int tid  = threadIdx.x;
    const int lane = tid & 31, warp = tid >> 5;
    const int g = lane >> 2, tig = lane & 3;
    const int mo = (warp >> 1) << 6;
    const int no = (warp & 1) << 6;
    const int brow = blockIdx.y << 7, bcol = blockIdx.x << 7;

    const int ar = tid >> 2, af = tid & 3;
    const int bk = tid >> 3, bc = tid & 7;

    float acc[4][8][4];
    #pragma unroll
    for (int mt = 0; mt < 4; mt++)
        #pragma unroll
        for (int nt = 0; nt < 8; nt++)
            #pragma unroll
            for (int i = 0; i < 4; i++) acc[mt][nt][i] = 0.f;

    float4 la[4], lb[4];

    #pragma unroll
    for (int rr = 0; rr < 4; rr++)
        la[rr] = *(const float4*)&A[(size_t)(brow + ar + 32*rr) * K + af*4];
    #pragma unroll
    for (int j = 0; j < 4; j++)
        lb[j] = *(const float4*)&W[(size_t)bk * N + bcol + (bc + 8*j)*4];
    #pragma unroll
    for (int rr = 0; rr < 4; rr++) {
        float4 v = la[rr];
        float4 t = make_float4(tf32r(v.x), tf32r(v.y), tf32r(v.z), tf32r(v.w));
        *(float4*)&As[0][(ar + 32*rr)*PADA + af*4] = t;
    }
    #pragma unroll
    for (int j = 0; j < 4; j++) {
        float4 v = lb[j];
        float4 t = make_float4(tf32r(v.x), tf32r(v.y), tf32r(v.z), tf32r(v.w));
        *(float4*)&Bs[0][bk*PADB + (bc + 8*j)*4] = t;
    }
    __syncthreads();

    const int iters = K >> 4;
    for (int it = 0; it < iters; ++it) {
        if (it + 1 < iters) {
            int k0 = (it + 1) << 4;
            #pragma unroll
            for (int rr = 0; rr < 4; rr++)
                la[rr] = *(const float4*)&A[(size_t)(brow + ar + 32*rr) * K + k0 + af*4];
            #pragma unroll
            for (int j = 0; j < 4; j++)
                lb[j] = *(const float4*)&W[(size_t)(k0 + bk) * N + bcol + (bc + 8*j)*4];
        }

        const float* as = As[it & 1];
        const float* bs = Bs[it & 1];
        #pragma unroll
        for (int ks = 0; ks < 2; ks++) {
            const int kb = ks*8 + tig;
            uint32_t afr[4][4], bfr[8][2];
            #pragma unroll
            for (int mt = 0; mt < 4; mt++) {
                int r0 = mo + mt*16 + g;
                afr[mt][0] = __float_as_uint(as[ r0     *PADA + kb    ]);
                afr[mt][1] = __float_as_uint(as[(r0 + 8)*PADA + kb    ]);
                afr[mt][2] = __float_as_uint(as[ r0     *PADA + kb + 4]);
                afr[mt][3] = __float_as_uint(as[(r0 + 8)*PADA + kb + 4]);
            }
            #pragma unroll
            for (int nt = 0; nt < 8; nt++) {
                int n = no + nt*8 + g;
                bfr[nt][0] = __float_as_uint(bs[ kb     *PADB + n]);
                bfr[nt][1] = __float_as_uint(bs[(kb + 4)*PADB + n]);
            }
            #pragma unroll
            for (int mt = 0; mt < 4; mt++)
                #pragma unroll
                for (int nt = 0; nt < 8; nt++)
                    mma_tf32(acc[mt][nt], afr[mt][0], afr[mt][1], afr[mt][2], afr[mt][3],
                             bfr[nt][0], bfr[nt][1]);
        }

        if (it + 1 < iters) {
            int nb = (it + 1) & 1;
            #pragma unroll
            for (int rr = 0; rr < 4; rr++) {
                float4 v = la[rr];
                float4 t = make_float4(tf32r(v.x), tf32r(v.y), tf32r(v.z), tf32r(v.w));
                *(float4*)&As[nb][(ar + 32*rr)*PADA + af*4] = t;
            }
            #pragma unroll
            for (int j = 0; j < 4; j++) {
                float4 v = lb[j];
                float4 t = make_float4(tf32r(v.x), tf32r(v.y), tf32r(v.z), tf32r(v.w));
                *(float4*)&Bs[nb][bk*PADB + (bc + 8*j)*4] = t;
            }
        }
        __syncthreads();
    }

    #pragma unroll
    for (int mt = 0; mt < 4; mt++) {
        int r0 = brow + mo + mt*16 + g;
        #pragma unroll
        for (int nt = 0; nt < 8; nt++) {
            int c = bcol + no + nt*8 + 2*tig;
            float b0 = bias[c], b1 = bias[c + 1];
            float2 v0 = make_float2(acc[mt][nt][0] + b0, acc[mt][nt][1] + b1);
            float2 v1 = make_float2(acc[mt][nt][2] + b0, acc[mt][nt][3] + b1);
            *(float2*)&C[(size_t)r0       * N + c] = v0;
            *(float2*)&C[(size_t)(r0 + 8) * N + c] = v1;
        }
    }
}

// ---------------- tensor-core flash attention ----------------
// grid: (T/128, H, 12=br*4+b); block 256 (8 warps x 16 query rows)
// smem: Qs[128][68], Ks[64][68], Vs[64][72], mask[64]
#define QPAD 68
#define KPAD 68
#define VPAD 72
#define SM_Q 0
#define SM_K (128*QPAD)              // 8704
#define SM_V (SM_K + 64*KPAD)        // 8704+4352=13056
#define SM_MS (SM_V + 64*VPAD)       // +4608 = 17664 floats
#define SMEM_ATTN_BYTES (SM_MS*4 + 64)

__global__ void __launch_bounds__(256)
attn_tc(const unsigned char* __restrict__ mask) {
    extern __shared__ float sm[];
    float* Qs = sm + SM_Q;
    float* Ks = sm + SM_K;
    float* Vs = sm + SM_V;
    unsigned char* ms = (unsigned char*)(sm + SM_MS);

    const int br = blockIdx.z >> 2;
    const int b  = blockIdx.z & 3;
    const int h  = blockIdx.y;
    const int q0 = blockIdx.x << 7;

    const int tid  = threadIdx.x;
    const int lane = tid & 31, warp = tid >> 5;
    const int g = lane >> 2, tig = lane & 3;
    const int mo = warp << 4;               // 16 query rows per warp
    const int lane_base = lane & ~3;

    // stage Q (scaled, tf32)
    const float* Qg = &g_q[(size_t)br*BTD + ((size_t)(b*TT + q0))*DD + h*HD];
    #pragma unroll
    for (int i = tid; i < 128*16; i += 256) {
        int row = i >> 4, c = (i & 15) * 4;
        float4 v = *(const float4*)&Qg[(size_t)row*DD + c];
        float4 t = make_float4(tf32r(v.x*0.125f), tf32r(v.y*0.125f),
                               tf32r(v.z*0.125f), tf32r(v.w*0.125f));
        *(float4*)&Qs[row*QPAD + c] = t;
    }

    float o[8][4];
    #pragma unroll
    for (int nt = 0; nt < 8; nt++)
        #pragma unroll
        for (int i = 0; i < 4; i++) o[nt][i] = 0.f;
    float m0 = -1e30f, m1 = -1e30f, l0 = 0.f, l1 = 0.f;

    const float* Kg = &g_k[((size_t)(b*NKV))*DD + h*HD];
    const float* Vg = &g_v[((size_t)(b*NKV))*DD + h*HD];

    for (int kc = 0; kc < NKV; kc += 64) {
        __syncthreads();
        #pragma unroll
        for (int i = tid; i < 64*16; i += 256) {
            int row = i >> 4, c = (i & 15) * 4;
            size_t gb2 = (size_t)(kc + row)*DD + c;
            float4 kv = *(const float4*)&Kg[gb2];
            float4 vv = *(const float4*)&Vg[gb2];
            *(float4*)&Ks[row*KPAD + c] = make_float4(tf32r(kv.x), tf32r(kv.y), tf32r(kv.z), tf32r(kv.w));
            *(float4*)&Vs[row*VPAD + c] = make_float4(tf32r(vv.x), tf32r(vv.y), tf32r(vv.z), tf32r(vv.w));
        }
        if (tid < 64) ms[tid] = mask[b*NKV + kc + tid];
        __syncthreads();

        // ---- S = Q @ K^T ----
        float s[8][4];
        #pragma unroll
        for (int nt = 0; nt < 8; nt++)
            #pragma unroll
            for (int i = 0; i < 4; i++) s[nt][i] = 0.f;

        #pragma unroll
        for (int ks = 0; ks < 8; ks++) {
            int kb = ks*8 + tig;
            uint32_t a0 = __float_as_uint(Qs[(mo + g    )*QPAD + kb    ]);
            uint32_t a1 = __float_as_uint(Qs[(mo + g + 8)*QPAD + kb    ]);
            uint32_t a2 = __float_as_uint(Qs[(mo + g    )*QPAD + kb + 4]);
            uint32_t a3 = __float_as_uint(Qs[(mo + g + 8)*QPAD + kb + 4]);
            #pragma unroll
            for (int nt = 0; nt < 8; nt++) {
                uint32_t b0 = __float_as_uint(Ks[(nt*8 + g)*KPAD + kb    ]);
                uint32_t b1 = __float_as_uint(Ks[(nt*8 + g)*KPAD + kb + 4]);
                mma_tf32(s[nt], a0, a1, a2, a3, b0, b1);
            }
        }

        // ---- mask + row max ----
        float rmax0 = -1e30f, rmax1 = -1e30f;
        #pragma unroll
        for (int nt = 0; nt < 8; nt++) {
            int c = nt*8 + 2*tig;
            if (ms[c    ]) { s[nt][0] = -1e30f; s[nt][2] = -1e30f; }
            if (ms[c + 1]) { s[nt][1] = -1e30f; s[nt][3] = -1e30f; }
            rmax0 = fmaxf(rmax0, fmaxf(s[nt][0], s[nt][1]));
            rmax1 = fmaxf(rmax1, fmaxf(s[nt][2], s[nt][3]));
        }
        #pragma unroll
        for (int off = 1; off <= 2; off <<= 1) {
            rmax0 = fmaxf(rmax0, __shfl_xor_sync(0xffffffffu, rmax0, off));
            rmax1 = fmaxf(rmax1, __shfl_xor_sync(0xffffffffu, rmax1, off));
        }
        float mn0 = fmaxf(m0, rmax0), mn1 = fmaxf(m1, rmax1);
        float f0 = __expf(m0 - mn0),  f1 = __expf(m1 - mn1);
        m0 = mn0; m1 = mn1;

        // ---- P = exp(S - m), row sums ----
        float rs0 = 0.f, rs1 = 0.f;
        #pragma unroll
        for (int nt = 0; nt < 8; nt++) {
            s[nt][0] = __expf(s[nt][0] - mn0);
            s[nt][1] = __expf(s[nt][1] - mn0);
            s[nt][2] = __expf(s[nt][2] - mn1);
            s[nt][3] = __expf(s[nt][3] - mn1);
            rs0 += s[nt][0] + s[nt][1];
            rs1 += s[nt][2] + s[nt][3];
            // convert to tf32 for the PV mma
            s[nt][0] = tf32r(s[nt][0]); s[nt][1] = tf32r(s[nt][1]);
            s[nt][2] = tf32r(s[nt][2]); s[nt][3] = tf32r(s[nt][3]);
        }
        #pragma unroll
        for (int off = 1; off <= 2; off <<= 1) {
            rs0 += __shfl_xor_sync(0xffffffffu, rs0, off);
            rs1 += __shfl_xor_sync(0xffffffffu, rs1, off);
        }
        l0 = l0 * f0 + rs0;
        l1 = l1 * f1 + rs1;

        // rescale O
        #pragma unroll
        for (int nt = 0; nt < 8; nt++) {
            o[nt][0] *= f0; o[nt][1] *= f0;
            o[nt][2] *= f1; o[nt][3] *= f1;
        }

        // ---- O += P @ V ----
        const int src1 = lane_base | (tig >> 1);
        const int src2 = lane_base | (2 + (tig >> 1));
        const bool odd = (tig & 1);
        #pragma unroll
        for (int kt = 0; kt < 8; kt++) {
            // quad transpose: accumulator layout -> A-operand layout
            float p0a = __shfl_sync(0xffffffffu, s[kt][0], src1);
            float p1a = __shfl_sync(0xffffffffu, s[kt][1], src1);
            float p2a = __shfl_sync(0xffffffffu, s[kt][2], src1);
            float p3a = __shfl_sync(0xffffffffu, s[kt][3], src1);
            float p0b = __shfl_sync(0xffffffffu, s[kt][0], src2);
            float p1b = __shfl_sync(0xffffffffu, s[kt][1], src2);
            float p2b = __shfl_sync(0xffffffffu, s[kt][2], src2);
            float p3b = __shfl_sync(0xffffffffu, s[kt][3], src2);
            uint32_t a0 = __float_as_uint(odd ? p1a : p0a);  // (g,   kt*8+tig)
            uint32_t a1 = __float_as_uint(odd ? p3a : p2a);  // (g+8, kt*8+tig)
            uint32_t a2 = __float_as_uint(odd ? p1b : p0b);  // (g,   kt*8+tig+4)
            uint32_t a3 = __float_as_uint(odd ? p3b : p2b);  // (g+8, kt*8+tig+4)
            #pragma unroll
            for (int nt = 0; nt < 8; nt++) {
                uint32_t b0 = __float_as_uint(Vs[(kt*8 + tig    )*VPAD + nt*8 + g]);
                uint32_t b1 = __float_as_uint(Vs[(kt*8 + tig + 4)*VPAD + nt*8 + g]);
                mma_tf32(o[nt], a0, a1, a2, a3, b0, b1);
            }
        }
    }

    float rl0 = (l0 > 0.f) ? 1.0f / l0 : 0.f;
    float rl1 = (l1 > 0.f) ? 1.0f / l1 : 0.f;
    float* Og = &g_ao[(size_t)br*BTD + ((size_t)(b*TT + q0))*DD + h*HD];
    #pragma unroll
    for (int nt = 0; nt < 8; nt++) {
        int c = nt*8 + 2*tig;
        float2 v0 = make_float2(o[nt][0]*rl0, o[nt][1]*rl0);
        float2 v1 = make_float2(o[nt][2]*rl1, o[nt][3]*rl1);
        *(float2*)&Og[(size_t)(mo + g    )*DD + c] = v0;
        *(float2*)&Og[(size_t)(mo + g + 8)*DD + c] = v1;
    }
}

// ---------------- launch ----------------
extern "C" void kernel_launch(void* const* d_in, const int* in_sizes, int n_in,
                              void* d_out, int out_size) {
    const float* x1        = (const float*)d_in[0];
    const float* x2        = (const float*)d_in[1];
    const float* x3        = (const float*)d_in[2];
    const float* xf        = (const float*)d_in[3];
    const float* emb       = (const float*)d_in[4];
    const unsigned char* mask = (const unsigned char*)d_in[5];
    const float* adaln_w   = (const float*)d_in[6];
    const float* adaln_b   = (const float*)d_in[7];
    const float* xf_adaln_w= (const float*)d_in[8];
    const float* xf_adaln_b= (const float*)d_in[9];
    const float* q_w       = (const float*)d_in[10];
    const float* q_b       = (const float*)d_in[11];
    const float* k_w       = (const float*)d_in[12];
    const float* k_b       = (const float*)d_in[13];
    const float* v_w       = (const float*)d_in[14];
    const float* v_b       = (const float*)d_in[15];
    const float* out_w     = (const float*)d_in[16];
    const float* out_b     = (const float*)d_in[17];
    float* out = (float*)d_out;

    float *hP, *qP, *kP, *vP, *aoP;
    cudaGetSymbolAddress((void**)&hP,  g_h);
    cudaGetSymbolAddress((void**)&qP,  g_q);
    cudaGetSymbolAddress((void**)&kP,  g_k);
    cudaGetSymbolAddress((void**)&vP,  g_v);
    cudaGetSymbolAddress((void**)&aoP, g_ao);

    static bool attr_set = false;
    if (!attr_set) {
        cudaFuncSetAttribute(attn_tc, cudaFuncAttributeMaxDynamicSharedMemorySize,
                             SMEM_ATTN_BYTES);
        attr_set = true;
    }

    silu_k<<<(BB*EE + 255)/256, 256>>>(emb);
    adaln_k<<<64, 256>>>(adaln_w, adaln_b, xf_adaln_w, xf_adaln_b);
    ln_mod_k<<<4 * BB * TT, 256>>>(x1, x2, x3, xf);

    // batched QKV projections: z = {Q0,Q1,Q2,K,V}
    GemmBatch gq;
    for (int i = 0; i < 3; i++) {
        gq.A[i] = hP + (size_t)i*BTD; gq.W[i] = q_w + (size_t)i*DD*DD;
        gq.bias[i] = q_b + i*DD;      gq.C[i] = qP + (size_t)i*BTD;
    }
    gq.A[3] = hP + (size_t)3*BTD; gq.W[3] = k_w; gq.bias[3] = k_b; gq.C[3] = kP;
    gq.A[4] = hP + (size_t)3*BTD; gq.W[4] = v_w; gq.bias[4] = v_b; gq.C[4] = vP;
    mma_gemm<<<dim3(DD/128, (BB*TT)/128, 5), 128>>>(gq, BB*TT, DD, DD);

    attn_tc<<<dim3(TT/128, HH, 3*BB), 256, SMEM_ATTN_BYTES>>>(mask);

    // batched output projections
    GemmBatch go;
    for (int i = 0; i < 3; i++) {
        go.A[i] = aoP + (size_t)i*BTD; go.W[i] = out_w + (size_t)i*DD*DD;
        go.bias[i] = out_b + i*DD;     go.C[i] = out + (size_t)i*BTD;
    }
    for (int i = 3; i < MAXZ; i++) { go.A[i] = nullptr; go.W[i] = nullptr; go.bias[i] = nullptr; go.C[i] = nullptr; }
    mma_gemm<<<dim3(DD/128, (BB*TT)/128, 3), 128>>>(go, BB*TT, DD, DD);
}

// round 4
// speedup vs baseline: 4.2019x; 1.0357x over previous
#include <cuda_runtime.h>
#include <cstdint>

#define BB 4
#define TT 512
#define NKV 512
#define DD 1024
#define EE 1024
#define HH 16
#define HD 64
#define BTD (BB*TT*DD)   // 2097152

// ---------------- scratch (static device memory; no allocation) ----------------
__device__ float g_eo[4][BB][2*DD];
__device__ float g_h [4*BTD];
__device__ float g_q [3*BTD];
__device__ float g_k [BTD];
__device__ float g_v [BTD];
__device__ float g_ao[3*BTD];
__device__ float g_wr[8*DD*DD];   // pre-rounded weights: Q0,Q1,Q2,K,V,O0,O1,O2

// ---------------- helpers ----------------
__device__ __forceinline__ float tf32r(float x) {
    uint32_t u;
    asm("cvt.rna.tf32.f32 %0, %1;" : "=r"(u) : "f"(x));
    return __uint_as_float(u);
}

__device__ __forceinline__ void mma_tf32(float c[4],
        uint32_t a0, uint32_t a1, uint32_t a2, uint32_t a3,
        uint32_t b0, uint32_t b1) {
    asm volatile("mma.sync.aligned.m16n8k8.row.col.f32.tf32.tf32.f32 "
        "{%0,%1,%2,%3}, {%4,%5,%6,%7}, {%8,%9}, {%0,%1,%2,%3};"
        : "+f"(c[0]), "+f"(c[1]), "+f"(c[2]), "+f"(c[3])
        : "r"(a0), "r"(a1), "r"(a2), "r"(a3), "r"(b0), "r"(b1));
}

__device__ __forceinline__ void cp16(uint32_t dst, const void* src) {
    asm volatile("cp.async.cg.shared.global [%0], [%1], 16;" :: "r"(dst), "l"(src));
}
__device__ __forceinline__ void cp_commit() {
    asm volatile("cp.async.commit_group;");
}

// ---------------- weight pre-round (fp32 -> tf32-rna) ----------------
__global__ void prep_w(const float* __restrict__ qw, const float* __restrict__ kw,
                       const float* __restrict__ vw, const float* __restrict__ ow) {
    int i4 = blockIdx.x * 256 + threadIdx.x;   // float4 index, 2M total
    int m = i4 >> 18;                          // 262144 float4 per matrix
    int r = i4 & 262143;
    const float* src;
    if (m < 3)      src = qw + ((size_t)m << 20);
    else if (m == 3) src = kw;
    else if (m == 4) src = vw;
    else             src = ow + ((size_t)(m - 5) << 20);
    float4 v = ((const float4*)src)[r];
    float4 t = make_float4(tf32r(v.x), tf32r(v.y), tf32r(v.z), tf32r(v.w));
    ((float4*)g_wr)[i4] = t;
}

// ---------------- adaln (silu fused) ----------------
__global__ void adaln_k(const float* __restrict__ emb,
                        const float* __restrict__ aw, const float* __restrict__ ab,
                        const float* __restrict__ xw, const float* __restrict__ xb) {
    int m = blockIdx.x >> 4;
    int oc = (blockIdx.x & 15) << 7;
    int o  = oc + (threadIdx.x & 127);
    int half = threadIdx.x >> 7;
    const float* Wm = (m < 3) ? aw + (size_t)m * EE * 2 * DD : xw;
    const float* Bm = (m < 3) ? ab + (size_t)m * 2 * DD      : xb;

    __shared__ float s[BB*EE];
    for (int i = threadIdx.x; i < BB*EE; i += 256) {
        float x = emb[i];
        s[i] = x / (1.0f + expf(-x));
    }
    __syncthreads();

    float acc[BB] = {0.f, 0.f, 0.f, 0.f};
    int e0 = half * 512;
    for (int e = e0; e < e0 + 512; e++) {
        float w = Wm[(size_t)e * 2 * DD + o];
        #pragma unroll
        for (int b = 0; b < BB; b++) acc[b] += s[b*EE + e] * w;
    }
    __shared__ float red[128][4];
    if (half) {
        #pragma unroll
        for (int b = 0; b < BB; b++) red[threadIdx.x & 127][b] = acc[b];
    }
    __syncthreads();
    if (!half) {
        float bias = Bm[o];
        #pragma unroll
        for (int b = 0; b < BB; b++)
            g_eo[m][b][o] = acc[b] + red[threadIdx.x][b] + bias;
    }
}

// ---------------- LN + modulate (writes tf32-rounded) ----------------
__global__ void ln_mod_k(const float* __restrict__ x1, const float* __restrict__ x2,
                         const float* __restrict__ x3, const float* __restrict__ xf) {
    int gr = blockIdx.x;
    int t  = gr >> 11;
    int r  = gr & 2047;
    int b  = r >> 9;

    const float* xp;
    switch (t) { case 0: xp = x1; break; case 1: xp = x2; break;
                 case 2: xp = x3; break; default: xp = xf; }
    xp += (size_t)r * DD;

    float v[4]; float s = 0.f, q = 0.f;
    #pragma unroll
    for (int i = 0; i < 4; i++) {
        v[i] = xp[threadIdx.x + 256*i];
        s += v[i]; q += v[i]*v[i];
    }
    #pragma unroll
    for (int off = 16; off > 0; off >>= 1) {
        s += __shfl_down_sync(0xffffffffu, s, off);
        q += __shfl_down_sync(0xffffffffu, q, off);
    }
    __shared__ float sh1[8], sh2[8];
    if ((threadIdx.x & 31) == 0) { sh1[threadIdx.x >> 5] = s; sh2[threadIdx.x >> 5] = q; }
    __syncthreads();
    __shared__ float mu_s, rstd_s;
    if (threadIdx.x == 0) {
        float S = 0.f, Q = 0.f;
        #pragma unroll
        for (int i = 0; i < 8; i++) { S += sh1[i]; Q += sh2[i]; }
        float mu  = S / (float)DD;
        float var = Q / (float)DD - mu*mu;
        mu_s = mu; rstd_s = rsqrtf(var + 1e-6f);
    }
    __syncthreads();
    float mu = mu_s, rstd = rstd_s;
    const float* eo = g_eo[t][b];
    float* hp = &g_h[(size_t)t*BTD + (size_t)r*DD];
    #pragma unroll
    for (int i = 0; i < 4; i++) {
        int d = threadIdx.x + 256*i;
        hp[d] = tf32r((v[i] - mu) * rstd * (1.0f + eo[d]) + eo[DD + d]);
    }
}

// ---------------- batched TF32 GEMM, cp.async staging, 256 threads ----------------
#define PADA 20
#define PADB 136
#define MAXZ 5

struct GemmBatch {
    const float* A[MAXZ];
    const float* W[MAXZ];
    const float* bias[MAXZ];
    float*       C[MAXZ];
};

__global__ void __launch_bounds__(256, 2)
mma_gemm(GemmBatch gb, int rnd, int N, int K) {
    __shared__ float As[2][128*PADA];
    __shared__ float Bs[2][16*PADB];

    const int z = blockIdx.z;
    const float* __restrict__ A    = gb.A[z];
    const float* __restrict__ W    = gb.W[z];
    const float* __restrict__ bias = gb.bias[z];
    float* __restrict__ C          = gb.C[z];

    const int tid  = threadIdx.x;
    const int lane = tid & 31, warp = tid >> 5;
    const int g = lane >> 2, tig = lane & 3;
    const int mo = (warp >> 2) << 6;      // 0 / 64
    const int no = (warp & 3) << 5;       // 0/32/64/96
    const int brow = blockIdx.y << 7, bcol = blockIdx.x << 7;

    const int ar = tid >> 2, af = tid & 3;    // A: rows ar, ar+64; float4 af
    const int bk = tid >> 4, bc = tid & 15;   // B: row bk; float4 cols bc, bc+16

    const uint32_t sA = (uint32_t)__cvta_generic_to_shared(&As[0][0]);
    const uint32_t sB = (uint32_t)__cvta_generic_to_shared(&Bs[0][0]);

    float acc[4][4][4];
    #pragma unroll
    for (int mt = 0; mt < 4; mt++)
        #pragma unroll
        for (int nt = 0; nt < 4; nt++)
            #pragma unroll
            for (int i = 0; i < 4; i++) acc[mt][nt][i] = 0.f;

    // prologue: tile 0 -> buf 0
    {
        cp16(sA + (ar*PADA + af*4)*4,        &A[(size_t)(brow + ar     ) * K + af*4]);
        cp16(sA + ((ar+64)*PADA + af*4)*4,   &A[(size_t)(brow + ar + 64) * K + af*4]);
        cp16(sB + (bk*PADB + bc*4)*4,        &W[(size_t)bk * N + bcol + bc*4]);
        cp16(sB + (bk*PADB + bc*4 + 64)*4,   &W[(size_t)bk * N + bcol + bc*4 + 64]);
        cp_commit();
    }

    const int iters = K >> 4;
    for (int it = 0; it < iters; ++it) {
        if (it + 1 < iters) {
            int k0 = (it + 1) << 4;
            uint32_t oA = sA + ((it + 1) & 1) * (128*PADA*4);
            uint32_t oB = sB + ((it + 1) & 1) * (16*PADB*4);
            cp16(oA + (ar*PADA + af*4)*4,        &A[(size_t)(brow + ar     ) * K + k0 + af*4]);
            cp16(oA + ((ar+64)*PADA + af*4)*4,   &A[(size_t)(brow + ar + 64) * K + k0 + af*4]);
            cp16(oB + (bk*PADB + bc*4)*4,        &W[(size_t)(k0 + bk) * N + bcol + bc*4]);
            cp16(oB + (bk*PADB + bc*4 + 64)*4,   &W[(size_t)(k0 + bk) * N + bcol + bc*4 + 64]);
            cp_commit();
            asm volatile("cp.async.wait_group 1;");
        } else {
            asm volatile("cp.async.wait_group 0;");
        }
        __syncthreads();

        const float* as = As[it & 1];
        const float* bs = Bs[it & 1];
        #pragma unroll
        for (int ks = 0; ks < 2; ks++) {
            const int kb = ks*8 + tig;
            uint32_t afr[4][4], bfr[4][2];
            #pragma unroll
            for (int mt = 0; mt < 4; mt++) {
                int r0 = mo + mt*16 + g;
                afr[mt][0] = __float_as_uint(as[ r0     *PADA + kb    ]);
                afr[mt][1] = __float_as_uint(as[(r0 + 8)*PADA + kb    ]);
                afr[mt][2] = __float_as_uint(as[ r0     *PADA + kb + 4]);
                afr[mt][3] = __float_as_uint(as[(r0 + 8)*PADA + kb + 4]);
            }
            #pragma unroll
            for (int nt = 0; nt < 4; nt++) {
                int n = no + nt*8 + g;
                bfr[nt][0] = __float_as_uint(bs[ kb     *PADB + n]);
                bfr[nt][1] = __float_as_uint(bs[(kb + 4)*PADB + n]);
            }
            #pragma unroll
            for (int mt = 0; mt < 4; mt++)
                #pragma unroll
                for (int nt = 0; nt < 4; nt++)
                    mma_tf32(acc[mt][nt], afr[mt][0], afr[mt][1], afr[mt][2], afr[mt][3],
                             bfr[nt][0], bfr[nt][1]);
        }
        __syncthreads();
    }

    #pragma unroll
    for (int mt = 0; mt < 4; mt++) {
        int r0 = brow + mo + mt*16 + g;
        #pragma unroll
        for (int nt = 0; nt < 4; nt++) {
            int c = bcol + no + nt*8 + 2*tig;
            float b0 = bias[c], b1 = bias[c + 1];
            float v00 = acc[mt][nt][0] + b0, v01 = acc[mt][nt][1] + b1;
            float v10 = acc[mt][nt][2] + b0, v11 = acc[mt][nt][3] + b1;
            if (rnd) { v00 = tf32r(v00); v01 = tf32r(v01); v10 = tf32r(v10); v11 = tf32r(v11); }
            *(float2*)&C[(size_t)r0       * N + c] = make_float2(v00, v01);
            *(float2*)&C[(size_t)(r0 + 8) * N + c] = make_float2(v10, v11);
        }
    }
}

// ---------------- tensor-core flash attention, cp.async double-buffered ----------------
#define QPAD 68
#define KPAD 68
#define VPAD 72
#define SM_Q  0
#define SM_K0 (128*QPAD)                 // 8704
#define KBUF  (64*KPAD)                  // 4352
#define SM_V0 (SM_K0 + 2*KBUF)           // 17408
#define VBUF  (64*VPAD)                  // 4608
#define SM_MS (SM_V0 + 2*VBUF)           // 26624
#define ATTN_WORDS (SM_MS + 128)         // 26752
#define SMEM_ATTN_BYTES (ATTN_WORDS*4)   // 107008

__global__ void __launch_bounds__(256)
attn_tc(const unsigned char* __restrict__ mask) {
    extern __shared__ float sm[];
    const uint32_t sbase = (uint32_t)__cvta_generic_to_shared(sm);

    const int br = blockIdx.z >> 2;
    const int b  = blockIdx.z & 3;
    const int h  = blockIdx.y;
    const int q0 = blockIdx.x << 7;

    const int tid  = threadIdx.x;
    const int lane = tid & 31, warp = tid >> 5;
    const int g = lane >> 2, tig = lane & 3;
    const int mo = warp << 4;
    const int lane_base = lane & ~3;

    const float* Qg = &g_q[(size_t)br*BTD + ((size_t)(b*TT + q0))*DD + h*HD];
    const float* Kg = &g_k[((size_t)(b*NKV))*DD + h*HD];
    const float* Vg = &g_v[((size_t)(b*NKV))*DD + h*HD];

    // prologue: Q + mask + K0/V0
    #pragma unroll
    for (int j = 0; j < 8; j++) {
        int i = tid + j*256;
        int row = i >> 4, c = (i & 15) * 4;
        cp16(sbase + (SM_Q + row*QPAD + c)*4, &Qg[(size_t)row*DD + c]);
    }
    if (tid < 32) cp16(sbase + SM_MS*4 + tid*16, mask + b*NKV + tid*16);
    #pragma unroll
    for (int j = 0; j < 4; j++) {
        int i = tid + j*256;
        int row = i >> 4, c = (i & 15) * 4;
        cp16(sbase + (SM_K0 + row*KPAD + c)*4, &Kg[(size_t)row*DD + c]);
        cp16(sbase + (SM_V0 + row*VPAD + c)*4, &Vg[(size_t)row*DD + c]);
    }
    cp_commit();

    float o[8][4];
    #pragma unroll
    for (int nt = 0; nt < 8; nt++)
        #pragma unroll
        for (int i = 0; i < 4; i++) o[nt][i] = 0.f;
    float m0 = -1e30f, m1 = -1e30f, l0 = 0.f, l1 = 0.f;

    const float* Qs = sm + SM_Q;

    for (int ci = 0; ci < 8; ci++) {
        const int kc = ci << 6;
        const int buf = ci & 1;
        if (ci < 7) {
            const int nb = buf ^ 1;
            #pragma unroll
            for (int j = 0; j < 4; j++) {
                int i = tid + j*256;
                int row = i >> 4, c = (i & 15) * 4;
                size_t gsrc = (size_t)(kc + 64 + row)*DD + c;
                cp16(sbase + (SM_K0 + nb*KBUF + row*KPAD + c)*4, &Kg[gsrc]);
                cp16(sbase + (SM_V0 + nb*VBUF + row*VPAD + c)*4, &Vg[gsrc]);
            }
            cp_commit();
            asm volatile("cp.async.wait_group 1;");
        } else {
            asm volatile("cp.async.wait_group 0;");
        }
        __syncthreads();

        const float* Ks = sm + SM_K0 + buf*KBUF;
        const float* Vs = sm + SM_V0 + buf*VBUF;
        const unsigned char* ms = (const unsigned char*)(sm + SM_MS) + kc;

        // ---- S = Q @ K^T ----
        float s[8][4];
        #pragma unroll
        for (int nt = 0; nt < 8; nt++)
            #pragma unroll
            for (int i = 0; i < 4; i++) s[nt][i] = 0.f;

        #pragma unroll
        for (int ks = 0; ks < 8; ks++) {
            int kb = ks*8 + tig;
            uint32_t a0 = __float_as_uint(Qs[(mo + g    )*QPAD + kb    ]);
            uint32_t a1 = __float_as_uint(Qs[(mo + g + 8)*QPAD + kb    ]);
            uint32_t a2 = __float_as_uint(Qs[(mo + g    )*QPAD + kb + 4]);
            uint32_t a3 = __float_as_uint(Qs[(mo + g + 8)*QPAD + kb + 4]);
            #pragma unroll
            for (int nt = 0; nt < 8; nt++) {
                uint32_t b0 = __float_as_uint(Ks[(nt*8 + g)*KPAD + kb    ]);
                uint32_t b1 = __float_as_uint(Ks[(nt*8 + g)*KPAD + kb + 4]);
                mma_tf32(s[nt], a0, a1, a2, a3, b0, b1);
            }
        }

        // ---- scale + mask + row max ----
        float rmax0 = -1e30f, rmax1 = -1e30f;
        #pragma unroll
        for (int nt = 0; nt < 8; nt++) {
            int c = nt*8 + 2*tig;
            s[nt][0] *= 0.125f; s[nt][1] *= 0.125f;
            s[nt][2] *= 0.125f; s[nt][3] *= 0.125f;
            if (ms[c    ]) { s[nt][0] = -1e30f; s[nt][2] = -1e30f; }
            if (ms[c + 1]) { s[nt][1] = -1e30f; s[nt][3] = -1e30f; }
            rmax0 = fmaxf(rmax0, fmaxf(s[nt][0], s[nt][1]));
            rmax1 = fmaxf(rmax1, fmaxf(s[nt][2], s[nt][3]));
        }
        #pragma unroll
        for (int off = 1; off <= 2; off <<= 1) {
            rmax0 = fmaxf(rmax0, __shfl_xor_sync(0xffffffffu, rmax0, off));
            rmax1 = fmaxf(rmax1, __shfl_xor_sync(0xffffffffu, rmax1, off));
        }
        float mn0 = fmaxf(m0, rmax0), mn1 = fmaxf(m1, rmax1);
        float f0 = __expf(m0 - mn0),  f1 = __expf(m1 - mn1);
        m0 = mn0; m1 = mn1;

        // ---- P = exp(S - m), row sums ----
        float rs0 = 0.f, rs1 = 0.f;
        #pragma unroll
        for (int nt = 0; nt < 8; nt++) {
            s[nt][0] = __expf(s[nt][0] - mn0);
            s[nt][1] = __expf(s[nt][1] - mn0);
            s[nt][2] = __expf(s[nt][2] - mn1);
            s[nt][3] = __expf(s[nt][3] - mn1);
            rs0 += s[nt][0] + s[nt][1];
            rs1 += s[nt][2] + s[nt][3];
            s[nt][0] = tf32r(s[nt][0]); s[nt][1] = tf32r(s[nt][1]);
            s[nt][2] = tf32r(s[nt][2]); s[nt][3] = tf32r(s[nt][3]);
        }
        #pragma unroll
        for (int off = 1; off <= 2; off <<= 1) {
            rs0 += __shfl_xor_sync(0xffffffffu, rs0, off);
            rs1 += __shfl_xor_sync(0xffffffffu, rs1, off);
        }
        l0 = l0 * f0 + rs0;
        l1 = l1 * f1 + rs1;

        #pragma unroll
        for (int nt = 0; nt < 8; nt++) {
            o[nt][0] *= f0; o[nt][1] *= f0;
            o[nt][2] *= f1; o[nt][3] *= f1;
        }

        // ---- O += P @ V (quad transpose of P) ----
        const int src1 = lane_base | (tig >> 1);
        const int src2 = lane_base | (2 + (tig >> 1));
        const bool odd = (tig & 1);
        #pragma unroll
        for (int kt = 0; kt < 8; kt++) {
            float p0a = __shfl_sync(0xffffffffu, s[kt][0], src1);
            float p1a = __shfl_sync(0xffffffffu, s[kt][1], src1);
            float p2a = __shfl_sync(0xffffffffu, s[kt][2], src1);
            float p3a = __shfl_sync(0xffffffffu, s[kt][3], src1);
            float p0b = __shfl_sync(0xffffffffu, s[kt][0], src2);
            float p1b = __shfl_sync(0xffffffffu, s[kt][1], src2);
            float p2b = __shfl_sync(0xffffffffu, s[kt][2], src2);
            float p3b = __shfl_sync(0xffffffffu, s[kt][3], src2);
            uint32_t a0 = __float_as_uint(odd ? p1a : p0a);
            uint32_t a1 = __float_as_uint(odd ? p3a : p2a);
            uint32_t a2 = __float_as_uint(odd ? p1b : p0b);
            uint32_t a3 = __float_as_uint(odd ? p3b : p2b);
            #pragma unroll
            for (int nt = 0; nt < 8; nt++) {
                uint32_t b0 = __float_as_uint(Vs[(kt*8 + tig    )*VPAD + nt*8 + g]);
                uint32_t b1 = __float_as_uint(Vs[(kt*8 + tig + 4)*VPAD + nt*8 + g]);
                mma_tf32(o[nt], a0, a1, a2, a3, b0, b1);
            }
        }
        __syncthreads();
    }

    float rl0 = (l0 > 0.f) ? 1.0f / l0 : 0.f;
    float rl1 = (l1 > 0.f) ? 1.0f / l1 : 0.f;
    float* Og = &g_ao[(size_t)br*BTD + ((size_t)(b*TT + q0))*DD + h*HD];
    #pragma unroll
    for (int nt = 0; nt < 8; nt++) {
        int c = nt*8 + 2*tig;
        float2 v0 = make_float2(tf32r(o[nt][0]*rl0), tf32r(o[nt][1]*rl0));
        float2 v1 = make_float2(tf32r(o[nt][2]*rl1), tf32r(o[nt][3]*rl1));
        *(float2*)&Og[(size_t)(mo + g    )*DD + c] = v0;
        *(float2*)&Og[(size_t)(mo + g + 8)*DD + c] = v1;
    }
}

// ---------------- launch ----------------
extern "C" void kernel_launch(void* const* d_in, const int* in_sizes, int n_in,
                              void* d_out, int out_size) {
    const float* x1        = (const float*)d_in[0];
    const float* x2        = (const float*)d_in[1];
    const float* x3        = (const float*)d_in[2];
    const float* xf        = (const float*)d_in[3];
    const float* emb       = (const float*)d_in[4];
    const unsigned char* mask = (const unsigned char*)d_in[5];
    const float* adaln_w   = (const float*)d_in[6];
    const float* adaln_b   = (const float*)d_in[7];
    const float* xf_adaln_w= (const float*)d_in[8];
    const float* xf_adaln_b= (const float*)d_in[9];
    const float* q_w       = (const float*)d_in[10];
    const float* q_b       = (const float*)d_in[11];
    const float* k_w       = (const float*)d_in[12];
    const float* k_b       = (const float*)d_in[13];
    const float* v_w       = (const float*)d_in[14];
    const float* v_b       = (const float*)d_in[15];
    const float* out_w     = (const float*)d_in[16];
    const float* out_b     = (const float*)d_in[17];
    float* out = (float*)d_out;

    float *hP, *qP, *kP, *vP, *aoP, *wrP;
    cudaGetSymbolAddress((void**)&hP,  g_h);
    cudaGetSymbolAddress((void**)&qP,  g_q);
    cudaGetSymbolAddress((void**)&kP,  g_k);
    cudaGetSymbolAddress((void**)&vP,  g_v);
    cudaGetSymbolAddress((void**)&aoP, g_ao);
    cudaGetSymbolAddress((void**)&wrP, g_wr);

    static bool attr_set = false;
    if (!attr_set) {
        cudaFuncSetAttribute(attn_tc, cudaFuncAttributeMaxDynamicSharedMemorySize,
                             SMEM_ATTN_BYTES);
        attr_set = true;
    }

    prep_w<<<8192, 256>>>(q_w, k_w, v_w, out_w);
    adaln_k<<<64, 256>>>(emb, adaln_w, adaln_b, xf_adaln_w, xf_adaln_b);
    ln_mod_k<<<4 * BB * TT, 256>>>(x1, x2, x3, xf);

    // batched QKV projections: z = {Q0,Q1,Q2,K,V}, rounded outputs
    GemmBatch gq;
    for (int i = 0; i < 3; i++) {
        gq.A[i] = hP + (size_t)i*BTD; gq.W[i] = wrP + (size_t)i*DD*DD;
        gq.bias[i] = q_b + i*DD;      gq.C[i] = qP + (size_t)i*BTD;
    }
    gq.A[3] = hP + (size_t)3*BTD; gq.W[3] = wrP + (size_t)3*DD*DD; gq.bias[3] = k_b; gq.C[3] = kP;
    gq.A[4] = hP + (size_t)3*BTD; gq.W[4] = wrP + (size_t)4*DD*DD; gq.bias[4] = v_b; gq.C[4] = vP;
    mma_gemm<<<dim3(DD/128, (BB*TT)/128, 5), 256>>>(gq, 1, DD, DD);

    attn_tc<<<dim3(TT/128, HH, 3*BB), 256, SMEM_ATTN_BYTES>>>(mask);

    // batched output projections, fp32 outputs
    GemmBatch go;
    for (int i = 0; i < 3; i++) {
        go.A[i] = aoP + (size_t)i*BTD; go.W[i] = wrP + (size_t)(5 + i)*DD*DD;
        go.bias[i] = out_b + i*DD;     go.C[i] = out + (size_t)i*BTD;
    }
    for (int i = 3; i < MAXZ; i++) { go.A[i] = nullptr; go.W[i] = nullptr; go.bias[i] = nullptr; go.C[i] = nullptr; }
    mma_gemm<<<dim3(DD/128, (BB*TT)/128, 3), 256>>>(go, 0, DD, DD);
}

// round 6
// speedup vs baseline: 6.2371x; 1.4843x over previous
#include <cuda_runtime.h>
#include <cuda_fp16.h>
#include <cstdint>

#define BB 4
#define TT 512
#define NKV 512
#define DD 1024
#define EE 1024
#define HH 16
#define HD 64
#define BTD (BB*TT*DD)   // 2097152

// ---------------- scratch (static device memory; no allocation) ----------------
__device__ float  g_eo[4][BB][2*DD];
__device__ __half g_h [4*BTD];
__device__ __half g_q [3*BTD];
__device__ __half g_k [BTD];
__device__ __half g_v [BTD];
__device__ __half g_ao[3*BTD];
__device__ __half g_wr[8*DD*DD];   // transposed fp16 weights [z][n][k]

// ---------------- helpers ----------------
__device__ __forceinline__ void mma_f16(float c[4],
        uint32_t a0, uint32_t a1, uint32_t a2, uint32_t a3,
        uint32_t b0, uint32_t b1) {
    asm volatile("mma.sync.aligned.m16n8k16.row.col.f32.f16.f16.f32 "
        "{%0,%1,%2,%3}, {%4,%5,%6,%7}, {%8,%9}, {%0,%1,%2,%3};"
        : "+f"(c[0]), "+f"(c[1]), "+f"(c[2]), "+f"(c[3])
        : "r"(a0), "r"(a1), "r"(a2), "r"(a3), "r"(b0), "r"(b1));
}
__device__ __forceinline__ void cp16(uint32_t dst, const void* src) {
    asm volatile("cp.async.cg.shared.global [%0], [%1], 16;" :: "r"(dst), "l"(src));
}
__device__ __forceinline__ void cp_commit() {
    asm volatile("cp.async.commit_group;");
}
__device__ __forceinline__ uint32_t packh2(float lo, float hi) {
    __half2 h = __floats2half2_rn(lo, hi);
    return *reinterpret_cast<uint32_t*>(&h);
}
__device__ __forceinline__ void ldsm_x4_t(uint32_t& r0, uint32_t& r1,
                                          uint32_t& r2, uint32_t& r3, uint32_t addr) {
    asm volatile("ldmatrix.sync.aligned.m8n8.x4.trans.shared.b16 {%0,%1,%2,%3}, [%4];"
        : "=r"(r0), "=r"(r1), "=r"(r2), "=r"(r3) : "r"(addr));
}

// ---------------- weight transpose + fp16: wr[z][n][k] = h(W[z][k][n]) ----------
__global__ void prep_wT(const float* __restrict__ qw, const float* __restrict__ kw,
                        const float* __restrict__ vw, const float* __restrict__ ow) {
    __shared__ float t[32][33];
    int z = blockIdx.z;
    const float* src;
    if (z < 3)       src = qw + (size_t)z * DD * DD;
    else if (z == 3) src = kw;
    else if (z == 4) src = vw;
    else             src = ow + (size_t)(z - 5) * DD * DD;
    int k0 = blockIdx.y * 32, n0 = blockIdx.x * 32;
    #pragma unroll
    for (int j = 0; j < 4; j++)
        t[threadIdx.y + j*8][threadIdx.x] = src[(size_t)(k0 + threadIdx.y + j*8)*DD + n0 + threadIdx.x];
    __syncthreads();
    __half* dst = g_wr + (size_t)z * DD * DD;
    #pragma unroll
    for (int j = 0; j < 4; j++)
        dst[(size_t)(n0 + threadIdx.y + j*8)*DD + k0 + threadIdx.x] =
            __float2half_rn(t[threadIdx.x][threadIdx.y + j*8]);
}

// ---------------- adaln (silu fused) ----------------
__global__ void adaln_k(const float* __restrict__ emb,
                        const float* __restrict__ aw, const float* __restrict__ ab,
                        const float* __restrict__ xw, const float* __restrict__ xb) {
    int m = blockIdx.x >> 4;
    int oc = (blockIdx.x & 15) << 7;
    int o  = oc + (threadIdx.x & 127);
    int half = threadIdx.x >> 7;
    const float* Wm = (m < 3) ? aw + (size_t)m * EE * 2 * DD : xw;
    const float* Bm = (m < 3) ? ab + (size_t)m * 2 * DD      : xb;

    __shared__ float s[BB*EE];
    for (int i = threadIdx.x; i < BB*EE; i += 256) {
        float x = emb[i];
        s[i] = x / (1.0f + expf(-x));
    }
    __syncthreads();

    float acc[BB] = {0.f, 0.f, 0.f, 0.f};
    int e0 = half * 512;
    for (int e = e0; e < e0 + 512; e++) {
        float w = Wm[(size_t)e * 2 * DD + o];
        #pragma unroll
        for (int b = 0; b < BB; b++) acc[b] += s[b*EE + e] * w;
    }
    __shared__ float red[128][4];
    if (half) {
        #pragma unroll
        for (int b = 0; b < BB; b++) red[threadIdx.x & 127][b] = acc[b];
    }
    __syncthreads();
    if (!half) {
        float bias = Bm[o];
        #pragma unroll
        for (int b = 0; b < BB; b++)
            g_eo[m][b][o] = acc[b] + red[threadIdx.x][b] + bias;
    }
}

// ---------------- LN + modulate (writes fp16) ----------------
__global__ void ln_mod_k(const float* __restrict__ x1, const float* __restrict__ x2,
                         const float* __restrict__ x3, const float* __restrict__ xf) {
    int gr = blockIdx.x;
    int t  = gr >> 11;
    int r  = gr & 2047;
    int b  = r >> 9;

    const float* xp;
    switch (t) { case 0: xp = x1; break; case 1: xp = x2; break;
                 case 2: xp = x3; break; default: xp = xf; }
    xp += (size_t)r * DD;

    float v[4]; float s = 0.f, q = 0.f;
    #pragma unroll
    for (int i = 0; i < 4; i++) {
        v[i] = xp[threadIdx.x + 256*i];
        s += v[i]; q += v[i]*v[i];
    }
    #pragma unroll
    for (int off = 16; off > 0; off >>= 1) {
        s += __shfl_down_sync(0xffffffffu, s, off);
        q += __shfl_down_sync(0xffffffffu, q, off);
    }
    __shared__ float sh1[8], sh2[8];
    if ((threadIdx.x & 31) == 0) { sh1[threadIdx.x >> 5] = s; sh2[threadIdx.x >> 5] = q; }
    __syncthreads();
    __shared__ float mu_s, rstd_s;
    if (threadIdx.x == 0) {
        float S = 0.f, Q = 0.f;
        #pragma unroll
        for (int i = 0; i < 8; i++) { S += sh1[i]; Q += sh2[i]; }
        float mu  = S / (float)DD;
        float var = Q / (float)DD - mu*mu;
        mu_s = mu; rstd_s = rsqrtf(var + 1e-6f);
    }
    __syncthreads();
    float mu = mu_s, rstd = rstd_s;
    const float* eo = g_eo[t][b];
    __half* hp = &g_h[(size_t)t*BTD + (size_t)r*DD];
    #pragma unroll
    for (int i = 0; i < 4; i++) {
        int d = threadIdx.x + 256*i;
        hp[d] = __float2half_rn((v[i] - mu) * rstd * (1.0f + eo[d]) + eo[DD + d]);
    }
}

// ---------------- batched FP16 GEMM (m16n8k16), cp.async double-buffered --------
// C[M,N] = A[M,K] @ Wt[N,K]^T + bias; CTA 128x128, BK=32 halves (64 B rows).
// smem rows padded to 40 halves (20 words) -> conflict-free frag loads.
#define HPA 40
#define MAXZ 5

struct GemmBatch {
    const __half* A[MAXZ];
    const __half* W[MAXZ];
    const float*  bias[MAXZ];
    void*         C[MAXZ];
};

__global__ void __launch_bounds__(256)
hgemm(GemmBatch gb, int toHalf, int N, int K) {
    __shared__ __half As[2][128*HPA];
    __shared__ __half Bs[2][128*HPA];

    const int z = blockIdx.z;
    const __half* __restrict__ A  = gb.A[z];
    const __half* __restrict__ Wt = gb.W[z];
    const float* __restrict__ bias = gb.bias[z];

    const int tid  = threadIdx.x;
    const int lane = tid & 31, warp = tid >> 5;
    const int g = lane >> 2, tig = lane & 3;
    const int mo = (warp >> 2) << 6;      // 0 / 64
    const int no = (warp & 3) << 5;       // 0/32/64/96
    const int brow = blockIdx.y << 7, bcol = blockIdx.x << 7;

    const uint32_t sA = (uint32_t)__cvta_generic_to_shared(&As[0][0]);
    const uint32_t sB = (uint32_t)__cvta_generic_to_shared(&Bs[0][0]);
    const int sm_ = tid >> 2, sq = tid & 3;   // stage: rows sm_, sm_+64; 16B piece sq

    float acc[4][4][4];
    #pragma unroll
    for (int mt = 0; mt < 4; mt++)
        #pragma unroll
        for (int nt = 0; nt < 4; nt++)
            #pragma unroll
            for (int i = 0; i < 4; i++) acc[mt][nt][i] = 0.f;

    auto stage = [&](int k0, int buf) {
        uint32_t oA = sA + buf * (128*HPA*2);
        uint32_t oB = sB + buf * (128*HPA*2);
        #pragma unroll
        for (int t = 0; t < 2; t++) {
            int m = sm_ + t*64;
            cp16(oA + m*(HPA*2) + sq*16, &A [(size_t)(brow + m)*K + k0 + sq*8]);
            cp16(oB + m*(HPA*2) + sq*16, &Wt[(size_t)(bcol + m)*K + k0 + sq*8]);
        }
        cp_commit();
    };

    stage(0, 0);

    const int iters = K >> 5;   // 32
    for (int it = 0; it < iters; ++it) {
        if (it + 1 < iters) {
            stage((it + 1) << 5, (it + 1) & 1);
            asm volatile("cp.async.wait_group 1;" ::: "memory");
        } else {
            asm volatile("cp.async.wait_group 0;" ::: "memory");
        }
        __syncthreads();

        const uint32_t* as = (const uint32_t*)As[it & 1];
        const uint32_t* bs = (const uint32_t*)Bs[it & 1];
        #pragma unroll
        for (int ks = 0; ks < 2; ks++) {
            const int ko = ks*8;
            uint32_t afr[4][4], bfr[4][2];
            #pragma unroll
            for (int mt = 0; mt < 4; mt++) {
                int r0 = mo + mt*16 + g;
                afr[mt][0] = as[ r0     *20 + ko + tig    ];
                afr[mt][1] = as[(r0 + 8)*20 + ko + tig    ];
                afr[mt][2] = as[ r0     *20 + ko + tig + 4];
                afr[mt][3] = as[(r0 + 8)*20 + ko + tig + 4];
            }
            #pragma unroll
            for (int nt = 0; nt < 4; nt++) {
                int n = no + nt*8 + g;
                bfr[nt][0] = bs[n*20 + ko + tig    ];
                bfr[nt][1] = bs[n*20 + ko + tig + 4];
            }
            #pragma unroll
            for (int mt = 0; mt < 4; mt++)
                #pragma unroll
                for (int nt = 0; nt < 4; nt++)
                    mma_f16(acc[mt][nt], afr[mt][0], afr[mt][1], afr[mt][2], afr[mt][3],
                            bfr[nt][0], bfr[nt][1]);
        }
        __syncthreads();
    }

    if (toHalf) {
        __half* C = (__half*)gb.C[z];
        #pragma unroll
        for (int mt = 0; mt < 4; mt++) {
            int r0 = brow + mo + mt*16 + g;
            #pragma unroll
            for (int nt = 0; nt < 4; nt++) {
                int c = bcol + no + nt*8 + 2*tig;
                float b0 = bias[c], b1 = bias[c + 1];
                uint32_t h0 = packh2(acc[mt][nt][0] + b0, acc[mt][nt][1] + b1);
                uint32_t h1 = packh2(acc[mt][nt][2] + b0, acc[mt][nt][3] + b1);
                *(uint32_t*)&C[(size_t)r0       * N + c] = h0;
                *(uint32_t*)&C[(size_t)(r0 + 8) * N + c] = h1;
            }
        }
    } else {
        float* C = (float*)gb.C[z];
        #pragma unroll
        for (int mt = 0; mt < 4; mt++) {
            int r0 = brow + mo + mt*16 + g;
            #pragma unroll
            for (int nt = 0; nt < 4; nt++) {
                int c = bcol + no + nt*8 + 2*tig;
                float b0 = bias[c], b1 = bias[c + 1];
                *(float2*)&C[(size_t)r0       * N + c] =
                    make_float2(acc[mt][nt][0] + b0, acc[mt][nt][1] + b1);
                *(float2*)&C[(size_t)(r0 + 8) * N + c] =
                    make_float2(acc[mt][nt][2] + b0, acc[mt][nt][3] + b1);
            }
        }
    }
}

// ---------------- FP16 flash attention, cp.async double-buffered ----------------
// smem word layout (4B words): Q[128][36w], K[2][64][36w], V[2][64][36w], mask
#define AQW   36
#define W_Q   0
#define W_K   4608
#define KWBUF 2304
#define W_V   9216
#define W_MS  13824
#define SMEM_ATTN_BYTES (W_MS*4 + 512)

__global__ void __launch_bounds__(256)
attn_tc(const unsigned char* __restrict__ mask) {
    extern __shared__ uint32_t sw[];
    const uint32_t sbase = (uint32_t)__cvta_generic_to_shared(sw);

    const int br = blockIdx.z >> 2;
    const int b  = blockIdx.z & 3;
    const int h  = blockIdx.y;
    const int q0 = blockIdx.x << 7;

    const int tid  = threadIdx.x;
    const int lane = tid & 31, warp = tid >> 5;
    const int g = lane >> 2, tig = lane & 3;
    const int mo = warp << 4;
    // ldmatrix.x4.trans lane mapping for V
    const int vr = (((lane >> 3) & 1) << 3) + (lane & 7);
    const int vc = (lane >> 4) << 3;

    const __half* Qg = &g_q[(size_t)br*BTD + ((size_t)(b*TT + q0))*DD + h*HD];
    const __half* Kg = &g_k[((size_t)(b*NKV))*DD + h*HD];
    const __half* Vg = &g_v[((size_t)(b*NKV))*DD + h*HD];

    // prologue: Q + mask + chunk0 K/V
    #pragma unroll
    for (int j = 0; j < 4; j++) {
        int u = tid + j*256;
        int row = u >> 3, q = u & 7;
        cp16(sbase + W_Q*4 + row*144 + q*16, &Qg[(size_t)row*DD + q*8]);
    }
    if (tid < 32) cp16(sbase + W_MS*4 + tid*16, mask + b*NKV + tid*16);
    #pragma unroll
    for (int j = 0; j < 2; j++) {
        int u = tid + j*256;
        int row = u >> 3, q = u & 7;
        cp16(sbase + W_K*4 + row*144 + q*16, &Kg[(size_t)row*DD + q*8]);
        cp16(sbase + W_V*4 + row*144 + q*16, &Vg[(size_t)row*DD + q*8]);
    }
    cp_commit();

    float o[8][4];
    #pragma unroll
    for (int nt = 0; nt < 8; nt++)
        #pragma unroll
        for (int i = 0; i < 4; i++) o[nt][i] = 0.f;
    float m0 = -1e30f, m1 = -1e30f, l0 = 0.f, l1 = 0.f;

    for (int ci = 0; ci < 8; ci++) {
        const int kc = ci << 6;
        const int buf = ci & 1;
        if (ci < 7) {
            const int nb = buf ^ 1;
            #pragma unroll
            for (int j = 0; j < 2; j++) {
                int u = tid + j*256;
                int row = u >> 3, q = u & 7;
                size_t gsrc = (size_t)(kc + 64 + row)*DD + q*8;
                cp16(sbase + (W_K + nb*KWBUF)*4 + row*144 + q*16, &Kg[gsrc]);
                cp16(sbase + (W_V + nb*KWBUF)*4 + row*144 + q*16, &Vg[gsrc]);
            }
            cp_commit();
            asm volatile("cp.async.wait_group 1;" ::: "memory");
        } else {
            asm volatile("cp.async.wait_group 0;" ::: "memory");
        }
        __syncthreads();

        const uint32_t kwb = W_K + buf*KWBUF;
        const unsigned char* ms = (const unsigned char*)(sw + W_MS) + kc;

        // ---- S = Q @ K^T ----
        float s[8][4];
        #pragma unroll
        for (int nt = 0; nt < 8; nt++)
            #pragma unroll
            for (int i = 0; i < 4; i++) s[nt][i] = 0.f;

        #pragma unroll
        for (int ks = 0; ks < 4; ks++) {
            const int ko = ks*8;
            uint32_t a0 = sw[W_Q + (mo + g    )*AQW + ko + tig    ];
            uint32_t a1 = sw[W_Q + (mo + g + 8)*AQW + ko + tig    ];
            uint32_t a2 = sw[W_Q + (mo + g    )*AQW + ko + tig + 4];
            uint32_t a3 = sw[W_Q + (mo + g + 8)*AQW + ko + tig + 4];
            #pragma unroll
            for (int nt = 0; nt < 8; nt++) {
                uint32_t b0 = sw[kwb + (nt*8 + g)*AQW + ko + tig    ];
                uint32_t b1 = sw[kwb + (nt*8 + g)*AQW + ko + tig + 4];
                mma_f16(s[nt], a0, a1, a2, a3, b0, b1);
            }
        }

        // ---- scale + mask + row max ----
        float rmax0 = -1e30f, rmax1 = -1e30f;
        #pragma unroll
        for (int nt = 0; nt < 8; nt++) {
            int c = nt*8 + 2*tig;
            s[nt][0] *= 0.125f; s[nt][1] *= 0.125f;
            s[nt][2] *= 0.125f; s[nt][3] *= 0.125f;
            if (ms[c    ]) { s[nt][0] = -1e30f; s[nt][2] = -1e30f; }
            if (ms[c + 1]) { s[nt][1] = -1e30f; s[nt][3] = -1e30f; }
            rmax0 = fmaxf(rmax0, fmaxf(s[nt][0], s[nt][1]));
            rmax1 = fmaxf(rmax1, fmaxf(s[nt][2], s[nt][3]));
        }
        #pragma unroll
        for (int off = 1; off <= 2; off <<= 1) {
            rmax0 = fmaxf(rmax0, __shfl_xor_sync(0xffffffffu, rmax0, off));
            rmax1 = fmaxf(rmax1, __shfl_xor_sync(0xffffffffu, rmax1, off));
        }
        float mn0 = fmaxf(m0, rmax0), mn1 = fmaxf(m1, rmax1);
        float f0 = __expf(m0 - mn0),  f1 = __expf(m1 - mn1);
        m0 = mn0; m1 = mn1;

        // ---- P = exp(S - m), row sums ----
        float rs0 = 0.f, rs1 = 0.f;
        #pragma unroll
        for (int nt = 0; nt < 8; nt++) {
            s[nt][0] = __expf(s[nt][0] - mn0);
            s[nt][1] = __expf(s[nt][1] - mn0);
            s[nt][2] = __expf(s[nt][2] - mn1);
            s[nt][3] = __expf(s[nt][3] - mn1);
            rs0 += s[nt][0] + s[nt][1];
            rs1 += s[nt][2] + s[nt][3];
        }
        #pragma unroll
        for (int off = 1; off <= 2; off <<= 1) {
            rs0 += __shfl_xor_sync(0xffffffffu, rs0, off);
            rs1 += __shfl_xor_sync(0xffffffffu, rs1, off);
        }
        l0 = l0 * f0 + rs0;
        l1 = l1 * f1 + rs1;

        #pragma unroll
        for (int nt = 0; nt < 8; nt++) {
            o[nt][0] *= f0; o[nt][1] *= f0;
            o[nt][2] *= f1; o[nt][3] *= f1;
        }

        // ---- O += P @ V ----
        // fp16 accumulator layout == A-operand layout: pack directly, no shuffles.
        const uint32_t vwb4 = (W_V + buf*KWBUF)*4;
        #pragma unroll
        for (int kt = 0; kt < 4; kt++) {
            uint32_t a0 = packh2(s[2*kt    ][0], s[2*kt    ][1]);
            uint32_t a1 = packh2(s[2*kt    ][2], s[2*kt    ][3]);
            uint32_t a2 = packh2(s[2*kt + 1][0], s[2*kt + 1][1]);
            uint32_t a3 = packh2(s[2*kt + 1][2], s[2*kt + 1][3]);
            #pragma unroll
            for (int np = 0; np < 4; np++) {
                uint32_t r0, r1, r2, r3;
                uint32_t addr = sbase + vwb4 + (kt*16 + vr)*144 + (np*16 + vc)*2;
                ldsm_x4_t(r0, r1, r2, r3, addr);
                mma_f16(o[2*np    ], a0, a1, a2, a3, r0, r1);
                mma_f16(o[2*np + 1], a0, a1, a2, a3, r2, r3);
            }
        }
        __syncthreads();
    }

    float rl0 = (l0 > 0.f) ? 1.0f / l0 : 0.f;
    float rl1 = (l1 > 0.f) ? 1.0f / l1 : 0.f;
    __half* Og = &g_ao[(size_t)br*BTD + ((size_t)(b*TT + q0))*DD + h*HD];
    #pragma unroll
    for (int nt = 0; nt < 8; nt++) {
        int c = nt*8 + 2*tig;
        uint32_t h0 = packh2(o[nt][0]*rl0, o[nt][1]*rl0);
        uint32_t h1 = packh2(o[nt][2]*rl1, o[nt][3]*rl1);
        *(uint32_t*)&Og[(size_t)(mo + g    )*DD + c] = h0;
        *(uint32_t*)&Og[(size_t)(mo + g + 8)*DD + c] = h1;
    }
}

// ---------------- launch ----------------
extern "C" void kernel_launch(void* const* d_in, const int* in_sizes, int n_in,
                              void* d_out, int out_size) {
    const float* x1        = (const float*)d_in[0];
    const float* x2        = (const float*)d_in[1];
    const float* x3        = (const float*)d_in[2];
    const float* xf        = (const float*)d_in[3];
    const float* emb       = (const float*)d_in[4];
    const unsigned char* mask = (const unsigned char*)d_in[5];
    const float* adaln_w   = (const float*)d_in[6];
    const float* adaln_b   = (const float*)d_in[7];
    const float* xf_adaln_w= (const float*)d_in[8];
    const float* xf_adaln_b= (const float*)d_in[9];
    const float* q_w       = (const float*)d_in[10];
    const float* q_b       = (const float*)d_in[11];
    const float* k_w       = (const float*)d_in[12];
    const float* k_b       = (const float*)d_in[13];
    const float* v_w       = (const float*)d_in[14];
    const float* v_b       = (const float*)d_in[15];
    const float* out_w     = (const float*)d_in[16];
    const float* out_b     = (const float*)d_in[17];
    float* out = (float*)d_out;

    __half *hP, *qP, *kP, *vP, *aoP, *wrP;
    cudaGetSymbolAddress((void**)&hP,  g_h);
    cudaGetSymbolAddress((void**)&qP,  g_q);
    cudaGetSymbolAddress((void**)&kP,  g_k);
    cudaGetSymbolAddress((void**)&vP,  g_v);
    cudaGetSymbolAddress((void**)&aoP, g_ao);
    cudaGetSymbolAddress((void**)&wrP, g_wr);

    static bool attr_set = false;
    if (!attr_set) {
        cudaFuncSetAttribute(attn_tc, cudaFuncAttributeMaxDynamicSharedMemorySize,
                             SMEM_ATTN_BYTES);
        attr_set = true;
    }

    prep_wT<<<dim3(32, 32, 8), dim3(32, 8)>>>(q_w, k_w, v_w, out_w);
    adaln_k<<<64, 256>>>(emb, adaln_w, adaln_b, xf_adaln_w, xf_adaln_b);
    ln_mod_k<<<4 * BB * TT, 256>>>(x1, x2, x3, xf);

    // batched QKV projections: z = {Q0,Q1,Q2,K,V}; fp16 outputs
    GemmBatch gq;
    for (int i = 0; i < 3; i++) {
        gq.A[i] = hP + (size_t)i*BTD; gq.W[i] = wrP + (size_t)i*DD*DD;
        gq.bias[i] = q_b + i*DD;      gq.C[i] = qP + (size_t)i*BTD;
    }
    gq.A[3] = hP + (size_t)3*BTD; gq.W[3] = wrP + (size_t)3*DD*DD; gq.bias[3] = k_b; gq.C[3] = kP;
    gq.A[4] = hP + (size_t)3*BTD; gq.W[4] = wrP + (size_t)4*DD*DD; gq.bias[4] = v_b; gq.C[4] = vP;
    hgemm<<<dim3(DD/128, (BB*TT)/128, 5), 256>>>(gq, 1, DD, DD);

    attn_tc<<<dim3(TT/128, HH, 3*BB), 256, SMEM_ATTN_BYTES>>>(mask);

    // batched output projections, fp32 outputs
    GemmBatch go;
    for (int i = 0; i < 3; i++) {
        go.A[i] = aoP + (size_t)i*BTD; go.W[i] = wrP + (size_t)(5 + i)*DD*DD;
        go.bias[i] = out_b + i*DD;     go.C[i] = out + (size_t)i*BTD;
    }
    for (int i = 3; i < MAXZ; i++) { go.A[i] = nullptr; go.W[i] = nullptr; go.bias[i] = nullptr; go.C[i] = nullptr; }
    hgemm<<<dim3(DD/128, (BB*TT)/128, 3), 256>>>(go, 0, DD, DD);
}

// round 7
// speedup vs baseline: 7.0140x; 1.1246x over previous
#include <cuda_runtime.h>
#include <cuda_fp16.h>
#include <cstdint>

#define BB 4
#define TT 512
#define NKV 512
#define DD 1024
#define EE 1024
#define HH 16
#define HD 64
#define BTD (BB*TT*DD)   // 2097152

// ---------------- scratch (static device memory; no allocation) ----------------
__device__ float  g_eo[4][BB][2*DD];
__device__ __half g_h [4*BTD];
__device__ __half g_q [3*BTD];
__device__ __half g_k [BTD];
__device__ __half g_v [BTD];
__device__ __half g_ao[3*BTD];
__device__ __half g_wr[8*DD*DD];   // transposed fp16 weights [z][n][k]

// ---------------- helpers ----------------
__device__ __forceinline__ void mma_f16(float c[4],
        uint32_t a0, uint32_t a1, uint32_t a2, uint32_t a3,
        uint32_t b0, uint32_t b1) {
    asm volatile("mma.sync.aligned.m16n8k16.row.col.f32.f16.f16.f32 "
        "{%0,%1,%2,%3}, {%4,%5,%6,%7}, {%8,%9}, {%0,%1,%2,%3};"
        : "+f"(c[0]), "+f"(c[1]), "+f"(c[2]), "+f"(c[3])
        : "r"(a0), "r"(a1), "r"(a2), "r"(a3), "r"(b0), "r"(b1));
}
__device__ __forceinline__ void cp16(uint32_t dst, const void* src) {
    asm volatile("cp.async.cg.shared.global [%0], [%1], 16;" :: "r"(dst), "l"(src));
}
__device__ __forceinline__ void cp_commit() {
    asm volatile("cp.async.commit_group;");
}
__device__ __forceinline__ uint32_t packh2(float lo, float hi) {
    __half2 h = __floats2half2_rn(lo, hi);
    return *reinterpret_cast<uint32_t*>(&h);
}
__device__ __forceinline__ void ldsm_x4(uint32_t& r0, uint32_t& r1,
                                        uint32_t& r2, uint32_t& r3, uint32_t addr) {
    asm volatile("ldmatrix.sync.aligned.m8n8.x4.shared.b16 {%0,%1,%2,%3}, [%4];"
        : "=r"(r0), "=r"(r1), "=r"(r2), "=r"(r3) : "r"(addr));
}
__device__ __forceinline__ void ldsm_x4_t(uint32_t& r0, uint32_t& r1,
                                          uint32_t& r2, uint32_t& r3, uint32_t addr) {
    asm volatile("ldmatrix.sync.aligned.m8n8.x4.trans.shared.b16 {%0,%1,%2,%3}, [%4];"
        : "=r"(r0), "=r"(r1), "=r"(r2), "=r"(r3) : "r"(addr));
}

// ---------------- weight transpose + fp16: wr[z][n][k] = h(W[z][k][n]) ----------
__global__ void prep_wT(const float* __restrict__ qw, const float* __restrict__ kw,
                        const float* __restrict__ vw, const float* __restrict__ ow) {
    __shared__ float t[32][33];
    int z = blockIdx.z;
    const float* src;
    if (z < 3)       src = qw + (size_t)z * DD * DD;
    else if (z == 3) src = kw;
    else if (z == 4) src = vw;
    else             src = ow + (size_t)(z - 5) * DD * DD;
    int k0 = blockIdx.y * 32, n0 = blockIdx.x * 32;
    #pragma unroll
    for (int j = 0; j < 4; j++)
        t[threadIdx.y + j*8][threadIdx.x] = src[(size_t)(k0 + threadIdx.y + j*8)*DD + n0 + threadIdx.x];
    __syncthreads();
    __half* dst = g_wr + (size_t)z * DD * DD;
    #pragma unroll
    for (int j = 0; j < 4; j++)
        dst[(size_t)(n0 + threadIdx.y + j*8)*DD + k0 + threadIdx.x] =
            __float2half_rn(t[threadIdx.x][threadIdx.y + j*8]);
}

// ---------------- adaln (silu fused) ----------------
__global__ void adaln_k(const float* __restrict__ emb,
                        const float* __restrict__ aw, const float* __restrict__ ab,
                        const float* __restrict__ xw, const float* __restrict__ xb) {
    int m = blockIdx.x >> 4;
    int oc = (blockIdx.x & 15) << 7;
    int o  = oc + (threadIdx.x & 127);
    int half = threadIdx.x >> 7;
    const float* Wm = (m < 3) ? aw + (size_t)m * EE * 2 * DD : xw;
    const float* Bm = (m < 3) ? ab + (size_t)m * 2 * DD      : xb;

    __shared__ float s[BB*EE];
    for (int i = threadIdx.x; i < BB*EE; i += 256) {
        float x = emb[i];
        s[i] = x / (1.0f + expf(-x));
    }
    __syncthreads();

    float acc[BB] = {0.f, 0.f, 0.f, 0.f};
    int e0 = half * 512;
    for (int e = e0; e < e0 + 512; e++) {
        float w = Wm[(size_t)e * 2 * DD + o];
        #pragma unroll
        for (int b = 0; b < BB; b++) acc[b] += s[b*EE + e] * w;
    }
    __shared__ float red[128][4];
    if (half) {
        #pragma unroll
        for (int b = 0; b < BB; b++) red[threadIdx.x & 127][b] = acc[b];
    }
    __syncthreads();
    if (!half) {
        float bias = Bm[o];
        #pragma unroll
        for (int b = 0; b < BB; b++)
            g_eo[m][b][o] = acc[b] + red[threadIdx.x][b] + bias;
    }
}

// ---------------- LN + modulate (writes fp16) ----------------
__global__ void ln_mod_k(const float* __restrict__ x1, const float* __restrict__ x2,
                         const float* __restrict__ x3, const float* __restrict__ xf) {
    int gr = blockIdx.x;
    int t  = gr >> 11;
    int r  = gr & 2047;
    int b  = r >> 9;

    const float* xp;
    switch (t) { case 0: xp = x1; break; case 1: xp = x2; break;
                 case 2: xp = x3; break; default: xp = xf; }
    xp += (size_t)r * DD;

    float v[4]; float s = 0.f, q = 0.f;
    #pragma unroll
    for (int i = 0; i < 4; i++) {
        v[i] = xp[threadIdx.x + 256*i];
        s += v[i]; q += v[i]*v[i];
    }
    #pragma unroll
    for (int off = 16; off > 0; off >>= 1) {
        s += __shfl_down_sync(0xffffffffu, s, off);
        q += __shfl_down_sync(0xffffffffu, q, off);
    }
    __shared__ float sh1[8], sh2[8];
    if ((threadIdx.x & 31) == 0) { sh1[threadIdx.x >> 5] = s; sh2[threadIdx.x >> 5] = q; }
    __syncthreads();
    __shared__ float mu_s, rstd_s;
    if (threadIdx.x == 0) {
        float S = 0.f, Q = 0.f;
        #pragma unroll
        for (int i = 0; i < 8; i++) { S += sh1[i]; Q += sh2[i]; }
        float mu  = S / (float)DD;
        float var = Q / (float)DD - mu*mu;
        mu_s = mu; rstd_s = rsqrtf(var + 1e-6f);
    }
    __syncthreads();
    float mu = mu_s, rstd = rstd_s;
    const float* eo = g_eo[t][b];
    __half* hp = &g_h[(size_t)t*BTD + (size_t)r*DD];
    #pragma unroll
    for (int i = 0; i < 4; i++) {
        int d = threadIdx.x + 256*i;
        hp[d] = __float2half_rn((v[i] - mu) * rstd * (1.0f + eo[d]) + eo[DD + d]);
    }
}

// ---------------- batched FP16 GEMM (m16n8k16), ldmatrix + BK=64 ----------------
// C[M,N] = A[M,K] @ Wt[N,K]^T + bias; CTA 128x128, BK=64 halves (128 B rows).
// smem rows padded to 72 halves (144 B): ldmatrix rows land on bank quads 4r%32.
#define HPA 72
#define HG_BUF   (128*HPA)            // halves per matrix per buffer
#define HG_STAGE (2*HG_BUF)           // A+B halves per buffer
#define HG_SMEM_BYTES (2*HG_STAGE*2)  // 73728 B
#define MAXZ 5

struct GemmBatch {
    const __half* A[MAXZ];
    const __half* W[MAXZ];
    const float*  bias[MAXZ];
    void*         C[MAXZ];
};

__global__ void __launch_bounds__(256, 2)
hgemm(GemmBatch gb, int toHalf, int N, int K) {
    extern __shared__ __half hsm[];
    const uint32_t sbase = (uint32_t)__cvta_generic_to_shared(hsm);

    const int z = blockIdx.z;
    const __half* __restrict__ A  = gb.A[z];
    const __half* __restrict__ Wt = gb.W[z];
    const float* __restrict__ bias = gb.bias[z];

    const int tid  = threadIdx.x;
    const int lane = tid & 31, warp = tid >> 5;
    const int g = lane >> 2, tig = lane & 3;
    const int mo = (warp >> 2) << 6;      // 0 / 64
    const int no = (warp & 3) << 5;       // 0/32/64/96
    const int brow = blockIdx.y << 7, bcol = blockIdx.x << 7;

    // ldmatrix per-lane geometry
    const int lr   = lane & 7;
    const int rA   = lr + ((lane >> 3) & 1) * 8;   // row within 16-row A tile
    const int khA  = (lane >> 4) * 8;              // k-half offset 0/8
    const int rB   = lr + (lane >> 4) * 8;         // row within 16-row B tile (nt pair)
    const int khB  = ((lane >> 3) & 1) * 8;

    // staging geometry: 128 rows x 8x16B pieces per matrix
    const int srow = tid >> 1;                     // unused split below
    (void)srow;

    float acc[4][4][4];
    #pragma unroll
    for (int mt = 0; mt < 4; mt++)
        #pragma unroll
        for (int nt = 0; nt < 4; nt++)
            #pragma unroll
            for (int i = 0; i < 4; i++) acc[mt][nt][i] = 0.f;

    auto stage = [&](int k0, int buf) {
        uint32_t oA = sbase + buf * (HG_STAGE*2);
        uint32_t oB = oA + HG_BUF*2;
        #pragma unroll
        for (int t = 0; t < 4; t++) {
            int u = tid + t*256;
            int row = u >> 3, piece = u & 7;
            cp16(oA + row*(HPA*2) + piece*16, &A [(size_t)(brow + row)*K + k0 + piece*8]);
        }
        #pragma unroll
        for (int t = 0; t < 4; t++) {
            int u = tid + t*256;
            int row = u >> 3, piece = u & 7;
            cp16(oB + row*(HPA*2) + piece*16, &Wt[(size_t)(bcol + row)*K + k0 + piece*8]);
        }
        cp_commit();
    };

    stage(0, 0);

    const int iters = K >> 6;   // 16
    for (int it = 0; it < iters; ++it) {
        if (it + 1 < iters) {
            stage((it + 1) << 6, (it + 1) & 1);
            asm volatile("cp.async.wait_group 1;" ::: "memory");
        } else {
            asm volatile("cp.async.wait_group 0;" ::: "memory");
        }
        __syncthreads();

        const uint32_t aB = sbase + (it & 1) * (HG_STAGE*2);
        const uint32_t bB = aB + HG_BUF*2;
        const uint32_t aAddr0 = aB + ((mo + rA)*HPA + khA)*2;
        const uint32_t bAddr0 = bB + ((no + rB)*HPA + khB)*2;

        #pragma unroll
        for (int ks = 0; ks < 4; ks++) {
            const int kh = ks*16*2;  // byte offset of k-step
            uint32_t afr[4][4], bfr[4][2];
            #pragma unroll
            for (int mt = 0; mt < 4; mt++)
                ldsm_x4(afr[mt][0], afr[mt][1], afr[mt][2], afr[mt][3],
                        aAddr0 + mt*(16*HPA*2) + kh);
            #pragma unroll
            for (int np = 0; np < 2; np++)
                ldsm_x4(bfr[2*np][0], bfr[2*np][1], bfr[2*np+1][0], bfr[2*np+1][1],
                        bAddr0 + np*(16*HPA*2) + kh);
            #pragma unroll
            for (int mt = 0; mt < 4; mt++)
                #pragma unroll
                for (int nt = 0; nt < 4; nt++)
                    mma_f16(acc[mt][nt], afr[mt][0], afr[mt][1], afr[mt][2], afr[mt][3],
                            bfr[nt][0], bfr[nt][1]);
        }
        __syncthreads();
    }

    if (toHalf) {
        __half* C = (__half*)gb.C[z];
        #pragma unroll
        for (int mt = 0; mt < 4; mt++) {
            int r0 = brow + mo + mt*16 + g;
            #pragma unroll
            for (int nt = 0; nt < 4; nt++) {
                int c = bcol + no + nt*8 + 2*tig;
                float b0 = bias[c], b1 = bias[c + 1];
                uint32_t h0 = packh2(acc[mt][nt][0] + b0, acc[mt][nt][1] + b1);
                uint32_t h1 = packh2(acc[mt][nt][2] + b0, acc[mt][nt][3] + b1);
                *(uint32_t*)&C[(size_t)r0       * N + c] = h0;
                *(uint32_t*)&C[(size_t)(r0 + 8) * N + c] = h1;
            }
        }
    } else {
        float* C = (float*)gb.C[z];
        #pragma unroll
        for (int mt = 0; mt < 4; mt++) {
            int r0 = brow + mo + mt*16 + g;
            #pragma unroll
            for (int nt = 0; nt < 4; nt++) {
                int c = bcol + no + nt*8 + 2*tig;
                float b0 = bias[c], b1 = bias[c + 1];
                *(float2*)&C[(size_t)r0       * N + c] =
                    make_float2(acc[mt][nt][0] + b0, acc[mt][nt][1] + b1);
                *(float2*)&C[(size_t)(r0 + 8) * N + c] =
                    make_float2(acc[mt][nt][2] + b0, acc[mt][nt][3] + b1);
            }
        }
    }
}

// ---------------- FP16 flash attention, ldmatrix everywhere ---------------------
// smem word layout (4B words): Q[128][36w], K[2][64][36w], V[2][64][36w], mask
#define AQW   36
#define W_Q   0
#define W_K   4608
#define KWBUF 2304
#define W_V   9216
#define W_MS  13824
#define SMEM_ATTN_BYTES (W_MS*4 + 512)

__global__ void __launch_bounds__(256)
attn_tc(const unsigned char* __restrict__ mask) {
    extern __shared__ uint32_t sw[];
    const uint32_t sbase = (uint32_t)__cvta_generic_to_shared(sw);

    const int br = blockIdx.z >> 2;
    const int b  = blockIdx.z & 3;
    const int h  = blockIdx.y;
    const int q0 = blockIdx.x << 7;

    const int tid  = threadIdx.x;
    const int lane = tid & 31, warp = tid >> 5;
    const int g = lane >> 2, tig = lane & 3;
    const int mo = warp << 4;

    // ldmatrix lane geometry (non-trans, A/B frags)
    const int lr  = lane & 7;
    const int rA  = lr + ((lane >> 3) & 1) * 8;
    const int khA = (lane >> 4) * 8;
    const int rB  = lr + (lane >> 4) * 8;
    const int khB = ((lane >> 3) & 1) * 8;
    // ldmatrix.x4.trans lane mapping for V
    const int vr = (((lane >> 3) & 1) << 3) + (lane & 7);
    const int vc = (lane >> 4) << 3;

    const __half* Qg = &g_q[(size_t)br*BTD + ((size_t)(b*TT + q0))*DD + h*HD];
    const __half* Kg = &g_k[((size_t)(b*NKV))*DD + h*HD];
    const __half* Vg = &g_v[((size_t)(b*NKV))*DD + h*HD];

    // prologue: Q + mask + chunk0 K/V
    #pragma unroll
    for (int j = 0; j < 4; j++) {
        int u = tid + j*256;
        int row = u >> 3, q = u & 7;
        cp16(sbase + W_Q*4 + row*144 + q*16, &Qg[(size_t)row*DD + q*8]);
    }
    if (tid < 32) cp16(sbase + W_MS*4 + tid*16, mask + b*NKV + tid*16);
    #pragma unroll
    for (int j = 0; j < 2; j++) {
        int u = tid + j*256;
        int row = u >> 3, q = u & 7;
        cp16(sbase + W_K*4 + row*144 + q*16, &Kg[(size_t)row*DD + q*8]);
        cp16(sbase + W_V*4 + row*144 + q*16, &Vg[(size_t)row*DD + q*8]);
    }
    cp_commit();

    float o[8][4];
    #pragma unroll
    for (int nt = 0; nt < 8; nt++)
        #pragma unroll
        for (int i = 0; i < 4; i++) o[nt][i] = 0.f;
    float m0 = -1e30f, m1 = -1e30f, l0 = 0.f, l1 = 0.f;

    const uint32_t qAddr0 = sbase + W_Q*4 + (mo + rA)*144 + khA*2;

    for (int ci = 0; ci < 8; ci++) {
        const int kc = ci << 6;
        const int buf = ci & 1;
        if (ci < 7) {
            const int nb = buf ^ 1;
            #pragma unroll
            for (int j = 0; j < 2; j++) {
                int u = tid + j*256;
                int row = u >> 3, q = u & 7;
                size_t gsrc = (size_t)(kc + 64 + row)*DD + q*8;
                cp16(sbase + (W_K + nb*KWBUF)*4 + row*144 + q*16, &Kg[gsrc]);
                cp16(sbase + (W_V + nb*KWBUF)*4 + row*144 + q*16, &Vg[gsrc]);
            }
            cp_commit();
            asm volatile("cp.async.wait_group 1;" ::: "memory");
        } else {
            asm volatile("cp.async.wait_group 0;" ::: "memory");
        }
        __syncthreads();

        const uint32_t kAddr0 = sbase + (W_K + buf*KWBUF)*4 + rB*144 + khB*2;
        const unsigned char* ms = (const unsigned char*)(sw + W_MS) + kc;

        // ---- S = Q @ K^T ----
        float s[8][4];
        #pragma unroll
        for (int nt = 0; nt < 8; nt++)
            #pragma unroll
            for (int i = 0; i < 4; i++) s[nt][i] = 0.f;

        #pragma unroll
        for (int ks = 0; ks < 4; ks++) {
            const int kh = ks*32;   // byte offset (16 halves)
            uint32_t a0, a1, a2, a3;
            ldsm_x4(a0, a1, a2, a3, qAddr0 + kh);
            #pragma unroll
            for (int np = 0; np < 4; np++) {
                uint32_t b0, b1, b2, b3;
                ldsm_x4(b0, b1, b2, b3, kAddr0 + np*(16*144) + kh);
                mma_f16(s[2*np    ], a0, a1, a2, a3, b0, b1);
                mma_f16(s[2*np + 1], a0, a1, a2, a3, b2, b3);
            }
        }

        // ---- scale + mask + row max ----
        float rmax0 = -1e30f, rmax1 = -1e30f;
        #pragma unroll
        for (int nt = 0; nt < 8; nt++) {
            int c = nt*8 + 2*tig;
            s[nt][0] *= 0.125f; s[nt][1] *= 0.125f;
            s[nt][2] *= 0.125f; s[nt][3] *= 0.125f;
            if (ms[c    ]) { s[nt][0] = -1e30f; s[nt][2] = -1e30f; }
            if (ms[c + 1]) { s[nt][1] = -1e30f; s[nt][3] = -1e30f; }
            rmax0 = fmaxf(rmax0, fmaxf(s[nt][0], s[nt][1]));
            rmax1 = fmaxf(rmax1, fmaxf(s[nt][2], s[nt][3]));
        }
        #pragma unroll
        for (int off = 1; off <= 2; off <<= 1) {
            rmax0 = fmaxf(rmax0, __shfl_xor_sync(0xffffffffu, rmax0, off));
            rmax1 = fmaxf(rmax1, __shfl_xor_sync(0xffffffffu, rmax1, off));
        }
        float mn0 = fmaxf(m0, rmax0), mn1 = fmaxf(m1, rmax1);
        float f0 = __expf(m0 - mn0),  f1 = __expf(m1 - mn1);
        m0 = mn0; m1 = mn1;

        // ---- P = exp(S - m), row sums ----
        float rs0 = 0.f, rs1 = 0.f;
        #pragma unroll
        for (int nt = 0; nt < 8; nt++) {
            s[nt][0] = __expf(s[nt][0] - mn0);
            s[nt][1] = __expf(s[nt][1] - mn0);
            s[nt][2] = __expf(s[nt][2] - mn1);
            s[nt][3] = __expf(s[nt][3] - mn1);
            rs0 += s[nt][0] + s[nt][1];
            rs1 += s[nt][2] + s[nt][3];
        }
        #pragma unroll
        for (int off = 1; off <= 2; off <<= 1) {
            rs0 += __shfl_xor_sync(0xffffffffu, rs0, off);
            rs1 += __shfl_xor_sync(0xffffffffu, rs1, off);
        }
        l0 = l0 * f0 + rs0;
        l1 = l1 * f1 + rs1;

        #pragma unroll
        for (int nt = 0; nt < 8; nt++) {
            o[nt][0] *= f0; o[nt][1] *= f0;
            o[nt][2] *= f1; o[nt][3] *= f1;
        }

        // ---- O += P @ V (fp16 acc layout == A-frag layout: direct pack) ----
        const uint32_t vwb4 = (W_V + buf*KWBUF)*4;
        #pragma unroll
        for (int kt = 0; kt < 4; kt++) {
            uint32_t a0 = packh2(s[2*kt    ][0], s[2*kt    ][1]);
            uint32_t a1 = packh2(s[2*kt    ][2], s[2*kt    ][3]);
            uint32_t a2 = packh2(s[2*kt + 1][0], s[2*kt + 1][1]);
            uint32_t a3 = packh2(s[2*kt + 1][2], s[2*kt + 1][3]);
            #pragma unroll
            for (int np = 0; np < 4; np++) {
                uint32_t r0, r1, r2, r3;
                uint32_t addr = sbase + vwb4 + (kt*16 + vr)*144 + (np*16 + vc)*2;
                ldsm_x4_t(r0, r1, r2, r3, addr);
                mma_f16(o[2*np    ], a0, a1, a2, a3, r0, r1);
                mma_f16(o[2*np + 1], a0, a1, a2, a3, r2, r3);
            }
        }
        __syncthreads();
    }

    float rl0 = (l0 > 0.f) ? 1.0f / l0 : 0.f;
    float rl1 = (l1 > 0.f) ? 1.0f / l1 : 0.f;
    __half* Og = &g_ao[(size_t)br*BTD + ((size_t)(b*TT + q0))*DD + h*HD];
    #pragma unroll
    for (int nt = 0; nt < 8; nt++) {
        int c = nt*8 + 2*tig;
        uint32_t h0 = packh2(o[nt][0]*rl0, o[nt][1]*rl0);
        uint32_t h1 = packh2(o[nt][2]*rl1, o[nt][3]*rl1);
        *(uint32_t*)&Og[(size_t)(mo + g    )*DD + c] = h0;
        *(uint32_t*)&Og[(size_t)(mo + g + 8)*DD + c] = h1;
    }
}

// ---------------- launch ----------------
extern "C" void kernel_launch(void* const* d_in, const int* in_sizes, int n_in,
                              void* d_out, int out_size) {
    const float* x1        = (const float*)d_in[0];
    const float* x2        = (const float*)d_in[1];
    const float* x3        = (const float*)d_in[2];
    const float* xf        = (const float*)d_in[3];
    const float* emb       = (const float*)d_in[4];
    const unsigned char* mask = (const unsigned char*)d_in[5];
    const float* adaln_w   = (const float*)d_in[6];
    const float* adaln_b   = (const float*)d_in[7];
    const float* xf_adaln_w= (const float*)d_in[8];
    const float* xf_adaln_b= (const float*)d_in[9];
    const float* q_w       = (const float*)d_in[10];
    const float* q_b       = (const float*)d_in[11];
    const float* k_w       = (const float*)d_in[12];
    const float* k_b       = (const float*)d_in[13];
    const float* v_w       = (const float*)d_in[14];
    const float* v_b       = (const float*)d_in[15];
    const float* out_w     = (const float*)d_in[16];
    const float* out_b     = (const float*)d_in[17];
    float* out = (float*)d_out;

    __half *hP, *qP, *kP, *vP, *aoP, *wrP;
    cudaGetSymbolAddress((void**)&hP,  g_h);
    cudaGetSymbolAddress((void**)&qP,  g_q);
    cudaGetSymbolAddress((void**)&kP,  g_k);
    cudaGetSymbolAddress((void**)&vP,  g_v);
    cudaGetSymbolAddress((void**)&aoP, g_ao);
    cudaGetSymbolAddress((void**)&wrP, g_wr);

    static bool attr_set = false;
    if (!attr_set) {
        cudaFuncSetAttribute(attn_tc, cudaFuncAttributeMaxDynamicSharedMemorySize,
                             SMEM_ATTN_BYTES);
        cudaFuncSetAttribute(hgemm, cudaFuncAttributeMaxDynamicSharedMemorySize,
                             HG_SMEM_BYTES);
        attr_set = true;
    }

    prep_wT<<<dim3(32, 32, 8), dim3(32, 8)>>>(q_w, k_w, v_w, out_w);
    adaln_k<<<64, 256>>>(emb, adaln_w, adaln_b, xf_adaln_w, xf_adaln_b);
    ln_mod_k<<<4 * BB * TT, 256>>>(x1, x2, x3, xf);

    // batched QKV projections: z = {Q0,Q1,Q2,K,V}; fp16 outputs
    GemmBatch gq;
    for (int i = 0; i < 3; i++) {
        gq.A[i] = hP + (size_t)i*BTD; gq.W[i] = wrP + (size_t)i*DD*DD;
        gq.bias[i] = q_b + i*DD;      gq.C[i] = qP + (size_t)i*BTD;
    }
    gq.A[3] = hP + (size_t)3*BTD; gq.W[3] = wrP + (size_t)3*DD*DD; gq.bias[3] = k_b; gq.C[3] = kP;
    gq.A[4] = hP + (size_t)3*BTD; gq.W[4] = wrP + (size_t)4*DD*DD; gq.bias[4] = v_b; gq.C[4] = vP;
    hgemm<<<dim3(DD/128, (BB*TT)/128, 5), 256, HG_SMEM_BYTES>>>(gq, 1, DD, DD);

    attn_tc<<<dim3(TT/128, HH, 3*BB), 256, SMEM_ATTN_BYTES>>>(mask);

    // batched output projections, fp32 outputs
    GemmBatch go;
    for (int i = 0; i < 3; i++) {
        go.A[i] = aoP + (size_t)i*BTD; go.W[i] = wrP + (size_t)(5 + i)*DD*DD;
        go.bias[i] = out_b + i*DD;     go.C[i] = out + (size_t)i*BTD;
    }
    for (int i = 3; i < MAXZ; i++) { go.A[i] = nullptr; go.W[i] = nullptr; go.bias[i] = nullptr; go.C[i] = nullptr; }
    hgemm<<<dim3(DD/128, (BB*TT)/128, 3), 256, HG_SMEM_BYTES>>>(go, 0, DD, DD);
}

// round 8
// speedup vs baseline: 7.1237x; 1.0156x over previous
#include <cuda_runtime.h>
#include <cuda_fp16.h>
#include <cstdint>

#define BB 4
#define TT 512
#define NKV 512
#define DD 1024
#define EE 1024
#define HH 16
#define HD 64
#define BTD (BB*TT*DD)   // 2097152

// ---------------- scratch (static device memory; no allocation) ----------------
__device__ float  g_eo[4][BB][2*DD];
__device__ __half g_h [4*BTD];
__device__ __half g_q [3*BTD];
__device__ __half g_k [BTD];
__device__ __half g_v [BTD];
__device__ __half g_ao[3*BTD];
__device__ __half g_wr[8*DD*DD];   // transposed fp16 weights [z][n][k]

// ---------------- helpers ----------------
__device__ __forceinline__ void mma_f16(float c[4],
        uint32_t a0, uint32_t a1, uint32_t a2, uint32_t a3,
        uint32_t b0, uint32_t b1) {
    asm volatile("mma.sync.aligned.m16n8k16.row.col.f32.f16.f16.f32 "
        "{%0,%1,%2,%3}, {%4,%5,%6,%7}, {%8,%9}, {%0,%1,%2,%3};"
        : "+f"(c[0]), "+f"(c[1]), "+f"(c[2]), "+f"(c[3])
        : "r"(a0), "r"(a1), "r"(a2), "r"(a3), "r"(b0), "r"(b1));
}
__device__ __forceinline__ void cp16(uint32_t dst, const void* src) {
    asm volatile("cp.async.cg.shared.global [%0], [%1], 16;" :: "r"(dst), "l"(src));
}
__device__ __forceinline__ void cp_commit() {
    asm volatile("cp.async.commit_group;");
}
__device__ __forceinline__ uint32_t packh2(float lo, float hi) {
    __half2 h = __floats2half2_rn(lo, hi);
    return *reinterpret_cast<uint32_t*>(&h);
}
__device__ __forceinline__ uint32_t ex2h2(uint32_t x) {
    uint32_t r;
    asm("ex2.approx.f16x2 %0, %1;" : "=r"(r) : "r"(x));
    return r;
}
__device__ __forceinline__ void ldsm_x4(uint32_t& r0, uint32_t& r1,
                                        uint32_t& r2, uint32_t& r3, uint32_t addr) {
    asm volatile("ldmatrix.sync.aligned.m8n8.x4.shared.b16 {%0,%1,%2,%3}, [%4];"
        : "=r"(r0), "=r"(r1), "=r"(r2), "=r"(r3) : "r"(addr));
}
__device__ __forceinline__ void ldsm_x4_t(uint32_t& r0, uint32_t& r1,
                                          uint32_t& r2, uint32_t& r3, uint32_t addr) {
    asm volatile("ldmatrix.sync.aligned.m8n8.x4.trans.shared.b16 {%0,%1,%2,%3}, [%4];"
        : "=r"(r0), "=r"(r1), "=r"(r2), "=r"(r3) : "r"(addr));
}

// ---------------- weight transpose + fp16: wr[z][n][k] = h(sc*W[z][k][n]) -------
__global__ void prep_wT(const float* __restrict__ qw, const float* __restrict__ kw,
                        const float* __restrict__ vw, const float* __restrict__ ow) {
    __shared__ float t[32][33];
    int z = blockIdx.z;
    const float* src;
    if (z < 3)       src = qw + (size_t)z * DD * DD;
    else if (z == 3) src = kw;
    else if (z == 4) src = vw;
    else             src = ow + (size_t)(z - 5) * DD * DD;
    float sc = (z < 3) ? 0.125f : 1.0f;   // fold softmax scale into Q weights
    int k0 = blockIdx.y * 32, n0 = blockIdx.x * 32;
    #pragma unroll
    for (int j = 0; j < 4; j++)
        t[threadIdx.y + j*8][threadIdx.x] = src[(size_t)(k0 + threadIdx.y + j*8)*DD + n0 + threadIdx.x];
    __syncthreads();
    __half* dst = g_wr + (size_t)z * DD * DD;
    #pragma unroll
    for (int j = 0; j < 4; j++)
        dst[(size_t)(n0 + threadIdx.y + j*8)*DD + k0 + threadIdx.x] =
            __float2half_rn(sc * t[threadIdx.x][threadIdx.y + j*8]);
}

// ---------------- adaln (silu fused) ----------------
__global__ void adaln_k(const float* __restrict__ emb,
                        const float* __restrict__ aw, const float* __restrict__ ab,
                        const float* __restrict__ xw, const float* __restrict__ xb) {
    int m = blockIdx.x >> 4;
    int oc = (blockIdx.x & 15) << 7;
    int o  = oc + (threadIdx.x & 127);
    int half = threadIdx.x >> 7;
    const float* Wm = (m < 3) ? aw + (size_t)m * EE * 2 * DD : xw;
    const float* Bm = (m < 3) ? ab + (size_t)m * 2 * DD      : xb;

    __shared__ float s[BB*EE];
    for (int i = threadIdx.x; i < BB*EE; i += 256) {
        float x = emb[i];
        s[i] = x / (1.0f + expf(-x));
    }
    __syncthreads();

    float acc[BB] = {0.f, 0.f, 0.f, 0.f};
    int e0 = half * 512;
    for (int e = e0; e < e0 + 512; e++) {
        float w = Wm[(size_t)e * 2 * DD + o];
        #pragma unroll
        for (int b = 0; b < BB; b++) acc[b] += s[b*EE + e] * w;
    }
    __shared__ float red[128][4];
    if (half) {
        #pragma unroll
        for (int b = 0; b < BB; b++) red[threadIdx.x & 127][b] = acc[b];
    }
    __syncthreads();
    if (!half) {
        float bias = Bm[o];
        #pragma unroll
        for (int b = 0; b < BB; b++)
            g_eo[m][b][o] = acc[b] + red[threadIdx.x][b] + bias;
    }
}

// ---------------- LN + modulate (writes fp16) ----------------
__global__ void ln_mod_k(const float* __restrict__ x1, const float* __restrict__ x2,
                         const float* __restrict__ x3, const float* __restrict__ xf) {
    int gr = blockIdx.x;
    int t  = gr >> 11;
    int r  = gr & 2047;
    int b  = r >> 9;

    const float* xp;
    switch (t) { case 0: xp = x1; break; case 1: xp = x2; break;
                 case 2: xp = x3; break; default: xp = xf; }
    xp += (size_t)r * DD;

    float v[4]; float s = 0.f, q = 0.f;
    #pragma unroll
    for (int i = 0; i < 4; i++) {
        v[i] = xp[threadIdx.x + 256*i];
        s += v[i]; q += v[i]*v[i];
    }
    #pragma unroll
    for (int off = 16; off > 0; off >>= 1) {
        s += __shfl_down_sync(0xffffffffu, s, off);
        q += __shfl_down_sync(0xffffffffu, q, off);
    }
    __shared__ float sh1[8], sh2[8];
    if ((threadIdx.x & 31) == 0) { sh1[threadIdx.x >> 5] = s; sh2[threadIdx.x >> 5] = q; }
    __syncthreads();
    __shared__ float mu_s, rstd_s;
    if (threadIdx.x == 0) {
        float S = 0.f, Q = 0.f;
        #pragma unroll
        for (int i = 0; i < 8; i++) { S += sh1[i]; Q += sh2[i]; }
        float mu  = S / (float)DD;
        float var = Q / (float)DD - mu*mu;
        mu_s = mu; rstd_s = rsqrtf(var + 1e-6f);
    }
    __syncthreads();
    float mu = mu_s, rstd = rstd_s;
    const float* eo = g_eo[t][b];
    __half* hp = &g_h[(size_t)t*BTD + (size_t)r*DD];
    #pragma unroll
    for (int i = 0; i < 4; i++) {
        int d = threadIdx.x + 256*i;
        hp[d] = __float2half_rn((v[i] - mu) * rstd * (1.0f + eo[d]) + eo[DD + d]);
    }
}

// ---------------- batched FP16 GEMM, ldmatrix + BK=64, 3-stage ring -------------
#define HPA 72
#define HG_BUF   (128*HPA)             // halves per matrix per buffer
#define HG_STAGE (2*HG_BUF)            // A+B halves per buffer
#define HG_SMEM_BYTES (3*HG_STAGE*2)   // 110592 B
#define MAXZ 5

struct GemmBatch {
    const __half* A[MAXZ];
    const __half* W[MAXZ];
    const float*  bias[MAXZ];
    float         bscale[MAXZ];
    void*         C[MAXZ];
};

__global__ void __launch_bounds__(256, 2)
hgemm(GemmBatch gb, int toHalf, int N, int K) {
    extern __shared__ __half hsm[];
    const uint32_t sbase = (uint32_t)__cvta_generic_to_shared(hsm);

    const int z = blockIdx.z;
    const __half* __restrict__ A  = gb.A[z];
    const __half* __restrict__ Wt = gb.W[z];
    const float* __restrict__ bias = gb.bias[z];
    const float bsc = gb.bscale[z];

    const int tid  = threadIdx.x;
    const int lane = tid & 31, warp = tid >> 5;
    const int g = lane >> 2, tig = lane & 3;
    const int mo = (warp >> 2) << 6;
    const int no = (warp & 3) << 5;
    const int brow = blockIdx.y << 7, bcol = blockIdx.x << 7;

    const int lr   = lane & 7;
    const int rA   = lr + ((lane >> 3) & 1) * 8;
    const int khA  = (lane >> 4) * 8;
    const int rB   = lr + (lane >> 4) * 8;
    const int khB  = ((lane >> 3) & 1) * 8;

    float acc[4][4][4];
    #pragma unroll
    for (int mt = 0; mt < 4; mt++)
        #pragma unroll
        for (int nt = 0; nt < 4; nt++)
            #pragma unroll
            for (int i = 0; i < 4; i++) acc[mt][nt][i] = 0.f;

    auto stage = [&](int k0, int buf) {
        uint32_t oA = sbase + buf * (HG_STAGE*2);
        uint32_t oB = oA + HG_BUF*2;
        #pragma unroll
        for (int t = 0; t < 4; t++) {
            int u = tid + t*256;
            int row = u >> 3, piece = u & 7;
            cp16(oA + row*(HPA*2) + piece*16, &A [(size_t)(brow + row)*K + k0 + piece*8]);
        }
        #pragma unroll
        for (int t = 0; t < 4; t++) {
            int u = tid + t*256;
            int row = u >> 3, piece = u & 7;
            cp16(oB + row*(HPA*2) + piece*16, &Wt[(size_t)(bcol + row)*K + k0 + piece*8]);
        }
        cp_commit();
    };

    stage(0, 0);
    stage(64, 1);

    const int iters = K >> 6;   // 16
    for (int it = 0; it < iters; ++it) {
        if (it + 2 < iters) {
            stage((it + 2) << 6, (it + 2) % 3);
            asm volatile("cp.async.wait_group 2;" ::: "memory");
        } else if (it + 1 < iters) {
            asm volatile("cp.async.wait_group 1;" ::: "memory");
        } else {
            asm volatile("cp.async.wait_group 0;" ::: "memory");
        }
        __syncthreads();

        const uint32_t aB = sbase + (it % 3) * (HG_STAGE*2);
        const uint32_t bB = aB + HG_BUF*2;
        const uint32_t aAddr0 = aB + ((mo + rA)*HPA + khA)*2;
        const uint32_t bAddr0 = bB + ((no + rB)*HPA + khB)*2;

        #pragma unroll
        for (int ks = 0; ks < 4; ks++) {
            const int kh = ks*16*2;
            uint32_t afr[4][4], bfr[4][2];
            #pragma unroll
            for (int mt = 0; mt < 4; mt++)
                ldsm_x4(afr[mt][0], afr[mt][1], afr[mt][2], afr[mt][3],
                        aAddr0 + mt*(16*HPA*2) + kh);
            #pragma unroll
            for (int np = 0; np < 2; np++)
                ldsm_x4(bfr[2*np][0], bfr[2*np][1], bfr[2*np+1][0], bfr[2*np+1][1],
                        bAddr0 + np*(16*HPA*2) + kh);
            #pragma unroll
            for (int mt = 0; mt < 4; mt++)
                #pragma unroll
                for (int nt = 0; nt < 4; nt++)
                    mma_f16(acc[mt][nt], afr[mt][0], afr[mt][1], afr[mt][2], afr[mt][3],
                            bfr[nt][0], bfr[nt][1]);
        }
        __syncthreads();
    }

    if (toHalf) {
        __half* C = (__half*)gb.C[z];
        #pragma unroll
        for (int mt = 0; mt < 4; mt++) {
            int r0 = brow + mo + mt*16 + g;
            #pragma unroll
            for (int nt = 0; nt < 4; nt++) {
                int c = bcol + no + nt*8 + 2*tig;
                float b0 = bias[c]*bsc, b1 = bias[c + 1]*bsc;
                uint32_t h0 = packh2(acc[mt][nt][0] + b0, acc[mt][nt][1] + b1);
                uint32_t h1 = packh2(acc[mt][nt][2] + b0, acc[mt][nt][3] + b1);
                *(uint32_t*)&C[(size_t)r0       * N + c] = h0;
                *(uint32_t*)&C[(size_t)(r0 + 8) * N + c] = h1;
            }
        }
    } else {
        float* C = (float*)gb.C[z];
        #pragma unroll
        for (int mt = 0; mt < 4; mt++) {
            int r0 = brow + mo + mt*16 + g;
            #pragma unroll
            for (int nt = 0; nt < 4; nt++) {
                int c = bcol + no + nt*8 + 2*tig;
                float b0 = bias[c], b1 = bias[c + 1];
                *(float2*)&C[(size_t)r0       * N + c] =
                    make_float2(acc[mt][nt][0] + b0, acc[mt][nt][1] + b1);
                *(float2*)&C[(size_t)(r0 + 8) * N + c] =
                    make_float2(acc[mt][nt][2] + b0, acc[mt][nt][3] + b1);
            }
        }
    }
}

// ---------------- FP16 flash attention: f16x2 exp, ones-col sums, hoisted Q -----
// smem word layout (4B words): Q[128][36w], K[2][64][36w], V[2][64][36w], mask
#define AQW   36
#define W_Q   0
#define W_K   4608
#define KWBUF 2304
#define W_V   9216
#define W_MS  13824
#define SMEM_ATTN_BYTES (W_MS*4 + 512)

__global__ void __launch_bounds__(256, 2)
attn_tc(const unsigned char* __restrict__ mask) {
    extern __shared__ uint32_t sw[];
    const uint32_t sbase = (uint32_t)__cvta_generic_to_shared(sw);

    const int br = blockIdx.z >> 2;
    const int b  = blockIdx.z & 3;
    const int h  = blockIdx.y;
    const int q0 = blockIdx.x << 7;

    const int tid  = threadIdx.x;
    const int lane = tid & 31, warp = tid >> 5;
    const int g = lane >> 2, tig = lane & 3;
    const int mo = warp << 4;

    const int lr  = lane & 7;
    const int rA  = lr + ((lane >> 3) & 1) * 8;
    const int khA = (lane >> 4) * 8;
    const int rB  = lr + (lane >> 4) * 8;
    const int khB = ((lane >> 3) & 1) * 8;
    const int vr = (((lane >> 3) & 1) << 3) + (lane & 7);
    const int vc = (lane >> 4) << 3;

    const __half* Qg = &g_q[(size_t)br*BTD + ((size_t)(b*TT + q0))*DD + h*HD];
    const __half* Kg = &g_k[((size_t)(b*NKV))*DD + h*HD];
    const __half* Vg = &g_v[((size_t)(b*NKV))*DD + h*HD];

    // prologue: Q + mask + chunk0 K/V (+ ones column in V)
    #pragma unroll
    for (int j = 0; j < 4; j++) {
        int u = tid + j*256;
        int row = u >> 3, q = u & 7;
        cp16(sbase + W_Q*4 + row*144 + q*16, &Qg[(size_t)row*DD + q*8]);
    }
    if (tid < 32) cp16(sbase + W_MS*4 + tid*16, mask + b*NKV + tid*16);
    #pragma unroll
    for (int j = 0; j < 2; j++) {
        int u = tid + j*256;
        int row = u >> 3, q = u & 7;
        cp16(sbase + W_K*4 + row*144 + q*16, &Kg[(size_t)row*DD + q*8]);
        cp16(sbase + W_V*4 + row*144 + q*16, &Vg[(size_t)row*DD + q*8]);
    }
    if (tid < 64)   // V cols 64-71 = {1,0,0,0,0,0,0,0}
        *(uint4*)((char*)sw + W_V*4 + tid*144 + 128) = make_uint4(0x00003C00u, 0u, 0u, 0u);
    cp_commit();

    asm volatile("cp.async.wait_group 0;" ::: "memory");
    __syncthreads();

    // hoist Q fragments (chunk-invariant)
    uint32_t qa[4][4];
    {
        const uint32_t qAddr0 = sbase + W_Q*4 + (mo + rA)*144 + khA*2;
        #pragma unroll
        for (int ks = 0; ks < 4; ks++)
            ldsm_x4(qa[ks][0], qa[ks][1], qa[ks][2], qa[ks][3], qAddr0 + ks*32);
    }

    float o[9][4];
    #pragma unroll
    for (int nt = 0; nt < 9; nt++)
        #pragma unroll
        for (int i = 0; i < 4; i++) o[nt][i] = 0.f;
    float m0 = -1e30f, m1 = -1e30f;
    const float L2E = 1.4426950408889634f;

    for (int ci = 0; ci < 8; ci++) {
        const int kc = ci << 6;
        const int buf = ci & 1;
        if (ci < 7) {
            const int nb = buf ^ 1;
            #pragma unroll
            for (int j = 0; j < 2; j++) {
                int u = tid + j*256;
                int row = u >> 3, q = u & 7;
                size_t gsrc = (size_t)(kc + 64 + row)*DD + q*8;
                cp16(sbase + (W_K + nb*KWBUF)*4 + row*144 + q*16, &Kg[gsrc]);
                cp16(sbase + (W_V + nb*KWBUF)*4 + row*144 + q*16, &Vg[gsrc]);
            }
            if (tid < 64)
                *(uint4*)((char*)sw + (W_V + nb*KWBUF)*4 + tid*144 + 128) =
                    make_uint4(0x00003C00u, 0u, 0u, 0u);
            cp_commit();
            asm volatile("cp.async.wait_group 1;" ::: "memory");
        } else {
            asm volatile("cp.async.wait_group 0;" ::: "memory");
        }
        __syncthreads();

        const uint32_t kAddr0 = sbase + (W_K + buf*KWBUF)*4 + rB*144 + khB*2;
        const unsigned char* ms = (const unsigned char*)(sw + W_MS) + kc;

        // ---- S = Q @ K^T (Q pre-scaled by 1/8 via weights) ----
        float s[8][4];
        #pragma unroll
        for (int nt = 0; nt < 8; nt++)
            #pragma unroll
            for (int i = 0; i < 4; i++) s[nt][i] = 0.f;

        #pragma unroll
        for (int ks = 0; ks < 4; ks++) {
            const int kh = ks*32;
            #pragma unroll
            for (int np = 0; np < 4; np++) {
                uint32_t b0, b1, b2, b3;
                ldsm_x4(b0, b1, b2, b3, kAddr0 + np*(16*144) + kh);
                mma_f16(s[2*np    ], qa[ks][0], qa[ks][1], qa[ks][2], qa[ks][3], b0, b1);
                mma_f16(s[2*np + 1], qa[ks][0], qa[ks][1], qa[ks][2], qa[ks][3], b2, b3);
            }
        }

        // ---- mask + row max ----
        float rmax0 = -1e30f, rmax1 = -1e30f;
        #pragma unroll
        for (int nt = 0; nt < 8; nt++) {
            int c = nt*8 + 2*tig;
            if (ms[c    ]) { s[nt][0] = -1e30f; s[nt][2] = -1e30f; }
            if (ms[c + 1]) { s[nt][1] = -1e30f; s[nt][3] = -1e30f; }
            rmax0 = fmaxf(rmax0, fmaxf(s[nt][0], s[nt][1]));
            rmax1 = fmaxf(rmax1, fmaxf(s[nt][2], s[nt][3]));
        }
        #pragma unroll
        for (int off = 1; off <= 2; off <<= 1) {
            rmax0 = fmaxf(rmax0, __shfl_xor_sync(0xffffffffu, rmax0, off));
            rmax1 = fmaxf(rmax1, __shfl_xor_sync(0xffffffffu, rmax1, off));
        }
        float mn0 = fmaxf(m0, rmax0), mn1 = fmaxf(m1, rmax1);
        float f0 = __expf(m0 - mn0),  f1 = __expf(m1 - mn1);
        m0 = mn0; m1 = mn1;
        float nm0 = mn0 * L2E, nm1 = mn1 * L2E;

        // ---- P = 2^((s-m)*log2e) in f16x2 (already A-frag packed) ----
        uint32_t pA[8], pB[8];
        #pragma unroll
        for (int nt = 0; nt < 8; nt++) {
            float t0 = fmaf(s[nt][0], L2E, -nm0);
            float t1 = fmaf(s[nt][1], L2E, -nm0);
            float t2 = fmaf(s[nt][2], L2E, -nm1);
            float t3 = fmaf(s[nt][3], L2E, -nm1);
            pA[nt] = ex2h2(packh2(t0, t1));
            pB[nt] = ex2h2(packh2(t2, t3));
        }

        // rescale O (incl. ones-column accumulator = running l)
        #pragma unroll
        for (int nt = 0; nt < 9; nt++) {
            o[nt][0] *= f0; o[nt][1] *= f0;
            o[nt][2] *= f1; o[nt][3] *= f1;
        }

        // ---- O += P @ V (np=4 covers the ones column -> row sums) ----
        const uint32_t vwb4 = (W_V + buf*KWBUF)*4;
        #pragma unroll
        for (int kt = 0; kt < 4; kt++) {
            uint32_t a0 = pA[2*kt], a1 = pB[2*kt], a2 = pA[2*kt+1], a3 = pB[2*kt+1];
            #pragma unroll
            for (int np = 0; np < 4; np++) {
                uint32_t r0, r1, r2, r3;
                uint32_t addr = sbase + vwb4 + (kt*16 + vr)*144 + (np*16 + vc)*2;
                ldsm_x4_t(r0, r1, r2, r3, addr);
                mma_f16(o[2*np    ], a0, a1, a2, a3, r0, r1);
                mma_f16(o[2*np + 1], a0, a1, a2, a3, r2, r3);
            }
            {   // ones column block (cols 64-71); r2,r3 (cols 72-79) unused
                uint32_t r0, r1, r2, r3;
                uint32_t addr = sbase + vwb4 + (kt*16 + vr)*144 + (64 + vc)*2;
                ldsm_x4_t(r0, r1, r2, r3, addr);
                mma_f16(o[8], a0, a1, a2, a3, r0, r1);
            }
        }
        __syncthreads();
    }

    // l lives in o[8][0]/o[8][2] of tig==0 lanes; broadcast within quad
    float lv0 = __shfl_sync(0xffffffffu, o[8][0], lane & ~3);
    float lv1 = __shfl_sync(0xffffffffu, o[8][2], lane & ~3);
    float rl0 = (lv0 > 0.f) ? 1.0f / lv0 : 0.f;
    float rl1 = (lv1 > 0.f) ? 1.0f / lv1 : 0.f;
    __half* Og = &g_ao[(size_t)br*BTD + ((size_t)(b*TT + q0))*DD + h*HD];
    #pragma unroll
    for (int nt = 0; nt < 8; nt++) {
        int c = nt*8 + 2*tig;
        uint32_t h0 = packh2(o[nt][0]*rl0, o[nt][1]*rl0);
        uint32_t h1 = packh2(o[nt][2]*rl1, o[nt][3]*rl1);
        *(uint32_t*)&Og[(size_t)(mo + g    )*DD + c] = h0;
        *(uint32_t*)&Og[(size_t)(mo + g + 8)*DD + c] = h1;
    }
}

// ---------------- launch ----------------
extern "C" void kernel_launch(void* const* d_in, const int* in_sizes, int n_in,
                              void* d_out, int out_size) {
    const float* x1        = (const float*)d_in[0];
    const float* x2        = (const float*)d_in[1];
    const float* x3        = (const float*)d_in[2];
    const float* xf        = (const float*)d_in[3];
    const float* emb       = (const float*)d_in[4];
    const unsigned char* mask = (const unsigned char*)d_in[5];
    const float* adaln_w   = (const float*)d_in[6];
    const float* adaln_b   = (const float*)d_in[7];
    const float* xf_adaln_w= (const float*)d_in[8];
    const float* xf_adaln_b= (const float*)d_in[9];
    const float* q_w       = (const float*)d_in[10];
    const float* q_b       = (const float*)d_in[11];
    const float* k_w       = (const float*)d_in[12];
    const float* k_b       = (const float*)d_in[13];
    const float* v_w       = (const float*)d_in[14];
    const float* v_b       = (const float*)d_in[15];
    const float* out_w     = (const float*)d_in[16];
    const float* out_b     = (const float*)d_in[17];
    float* out = (float*)d_out;

    __half *hP, *qP, *kP, *vP, *aoP, *wrP;
    cudaGetSymbolAddress((void**)&hP,  g_h);
    cudaGetSymbolAddress((void**)&qP,  g_q);
    cudaGetSymbolAddress((void**)&kP,  g_k);
    cudaGetSymbolAddress((void**)&vP,  g_v);
    cudaGetSymbolAddress((void**)&aoP, g_ao);
    cudaGetSymbolAddress((void**)&wrP, g_wr);

    static bool attr_set = false;
    if (!attr_set) {
        cudaFuncSetAttribute(attn_tc, cudaFuncAttributeMaxDynamicSharedMemorySize,
                             SMEM_ATTN_BYTES);
        cudaFuncSetAttribute(hgemm, cudaFuncAttributeMaxDynamicSharedMemorySize,
                             HG_SMEM_BYTES);
        attr_set = true;
    }

    prep_wT<<<dim3(32, 32, 8), dim3(32, 8)>>>(q_w, k_w, v_w, out_w);
    adaln_k<<<64, 256>>>(emb, adaln_w, adaln_b, xf_adaln_w, xf_adaln_b);
    ln_mod_k<<<4 * BB * TT, 256>>>(x1, x2, x3, xf);

    // batched QKV projections: z = {Q0,Q1,Q2,K,V}; fp16 outputs; Q bias scaled 1/8
    GemmBatch gq;
    for (int i = 0; i < 3; i++) {
        gq.A[i] = hP + (size_t)i*BTD; gq.W[i] = wrP + (size_t)i*DD*DD;
        gq.bias[i] = q_b + i*DD;      gq.C[i] = qP + (size_t)i*BTD;
        gq.bscale[i] = 0.125f;
    }
    gq.A[3] = hP + (size_t)3*BTD; gq.W[3] = wrP + (size_t)3*DD*DD; gq.bias[3] = k_b; gq.C[3] = kP; gq.bscale[3] = 1.0f;
    gq.A[4] = hP + (size_t)3*BTD; gq.W[4] = wrP + (size_t)4*DD*DD; gq.bias[4] = v_b; gq.C[4] = vP; gq.bscale[4] = 1.0f;
    hgemm<<<dim3(DD/128, (BB*TT)/128, 5), 256, HG_SMEM_BYTES>>>(gq, 1, DD, DD);

    attn_tc<<<dim3(TT/128, HH, 3*BB), 256, SMEM_ATTN_BYTES>>>(mask);

    // batched output projections, fp32 outputs
    GemmBatch go;
    for (int i = 0; i < 3; i++) {
        go.A[i] = aoP + (size_t)i*BTD; go.W[i] = wrP + (size_t)(5 + i)*DD*DD;
        go.bias[i] = out_b + i*DD;     go.C[i] = out + (size_t)i*BTD;
        go.bscale[i] = 1.0f;
    }
    for (int i = 3; i < MAXZ; i++) { go.A[i] = nullptr; go.W[i] = nullptr; go.bias[i] = nullptr; go.C[i] = nullptr; go.bscale[i] = 1.0f; }
    hgemm<<<dim3(DD/128, (BB*TT)/128, 3), 256, HG_SMEM_BYTES>>>(go, 0, DD, DD);
}

// round 9
// speedup vs baseline: 7.2208x; 1.0136x over previous
#include <cuda_runtime.h>
#include <cuda_fp16.h>
#include <cstdint>

#define BB 4
#define TT 512
#define NKV 512
#define DD 1024
#define EE 1024
#define HH 16
#define HD 64
#define BTD (BB*TT*DD)   // 2097152

// ---------------- scratch (static device memory; no allocation) ----------------
__device__ float  g_eo[4][BB][2*DD];
__device__ __half g_h [4*BTD];
__device__ __half g_q [3*BTD];
__device__ __half g_k [BTD];
__device__ __half g_v [BTD];
__device__ __half g_ao[3*BTD];
__device__ __half g_wr[8*DD*DD];   // fp16 weights, K-major [z][k][n] (pre-scaled for Q)

// ---------------- helpers ----------------
__device__ __forceinline__ void mma_f16(float c[4],
        uint32_t a0, uint32_t a1, uint32_t a2, uint32_t a3,
        uint32_t b0, uint32_t b1) {
    asm volatile("mma.sync.aligned.m16n8k16.row.col.f32.f16.f16.f32 "
        "{%0,%1,%2,%3}, {%4,%5,%6,%7}, {%8,%9}, {%0,%1,%2,%3};"
        : "+f"(c[0]), "+f"(c[1]), "+f"(c[2]), "+f"(c[3])
        : "r"(a0), "r"(a1), "r"(a2), "r"(a3), "r"(b0), "r"(b1));
}
__device__ __forceinline__ void cp16(uint32_t dst, const void* src) {
    asm volatile("cp.async.cg.shared.global [%0], [%1], 16;" :: "r"(dst), "l"(src));
}
__device__ __forceinline__ void cp_commit() {
    asm volatile("cp.async.commit_group;");
}
__device__ __forceinline__ uint32_t packh2(float lo, float hi) {
    __half2 h = __floats2half2_rn(lo, hi);
    return *reinterpret_cast<uint32_t*>(&h);
}
__device__ __forceinline__ uint32_t ex2h2(uint32_t x) {
    uint32_t r;
    asm("ex2.approx.f16x2 %0, %1;" : "=r"(r) : "r"(x));
    return r;
}
__device__ __forceinline__ void ldsm_x4(uint32_t& r0, uint32_t& r1,
                                        uint32_t& r2, uint32_t& r3, uint32_t addr) {
    asm volatile("ldmatrix.sync.aligned.m8n8.x4.shared.b16 {%0,%1,%2,%3}, [%4];"
        : "=r"(r0), "=r"(r1), "=r"(r2), "=r"(r3) : "r"(addr));
}
__device__ __forceinline__ void ldsm_x4_t(uint32_t& r0, uint32_t& r1,
                                          uint32_t& r2, uint32_t& r3, uint32_t addr) {
    asm volatile("ldmatrix.sync.aligned.m8n8.x4.trans.shared.b16 {%0,%1,%2,%3}, [%4];"
        : "=r"(r0), "=r"(r1), "=r"(r2), "=r"(r3) : "r"(addr));
}

// ---------------- weight convert (K-major, scaled): wr[z][k][n] = h(sc*W) --------
__global__ void prep_w(const float* __restrict__ qw, const float* __restrict__ kw,
                       const float* __restrict__ vw, const float* __restrict__ ow) {
    int idx = blockIdx.x * 256 + threadIdx.x;     // 1M threads, 8 halves each
    int z = idx >> 17;                            // 131072 groups per matrix
    int r = idx & 131071;
    const float* src;
    if (z < 3)       src = qw + (size_t)z * DD * DD;
    else if (z == 3) src = kw;
    else if (z == 4) src = vw;
    else             src = ow + (size_t)(z - 5) * DD * DD;
    float sc = (z < 3) ? 0.125f : 1.0f;           // fold softmax scale into Q weights
    float4 v0 = ((const float4*)src)[r*2];
    float4 v1 = ((const float4*)src)[r*2 + 1];
    uint4 o;
    o.x = packh2(sc*v0.x, sc*v0.y);
    o.y = packh2(sc*v0.z, sc*v0.w);
    o.z = packh2(sc*v1.x, sc*v1.y);
    o.w = packh2(sc*v1.z, sc*v1.w);
    ((uint4*)(g_wr + (size_t)z * DD * DD))[r] = o;
}

// ---------------- adaln (silu fused) ----------------
__global__ void adaln_k(const float* __restrict__ emb,
                        const float* __restrict__ aw, const float* __restrict__ ab,
                        const float* __restrict__ xw, const float* __restrict__ xb) {
    int m = blockIdx.x >> 4;
    int oc = (blockIdx.x & 15) << 7;
    int o  = oc + (threadIdx.x & 127);
    int half = threadIdx.x >> 7;
    const float* Wm = (m < 3) ? aw + (size_t)m * EE * 2 * DD : xw;
    const float* Bm = (m < 3) ? ab + (size_t)m * 2 * DD      : xb;

    __shared__ float s[BB*EE];
    for (int i = threadIdx.x; i < BB*EE; i += 256) {
        float x = emb[i];
        s[i] = x / (1.0f + expf(-x));
    }
    __syncthreads();

    float acc[BB] = {0.f, 0.f, 0.f, 0.f};
    int e0 = half * 512;
    for (int e = e0; e < e0 + 512; e++) {
        float w = Wm[(size_t)e * 2 * DD + o];
        #pragma unroll
        for (int b = 0; b < BB; b++) acc[b] += s[b*EE + e] * w;
    }
    __shared__ float red[128][4];
    if (half) {
        #pragma unroll
        for (int b = 0; b < BB; b++) red[threadIdx.x & 127][b] = acc[b];
    }
    __syncthreads();
    if (!half) {
        float bias = Bm[o];
        #pragma unroll
        for (int b = 0; b < BB; b++)
            g_eo[m][b][o] = acc[b] + red[threadIdx.x][b] + bias;
    }
}

// ---------------- LN + modulate (writes fp16) ----------------
__global__ void ln_mod_k(const float* __restrict__ x1, const float* __restrict__ x2,
                         const float* __restrict__ x3, const float* __restrict__ xf) {
    int gr = blockIdx.x;
    int t  = gr >> 11;
    int r  = gr & 2047;
    int b  = r >> 9;

    const float* xp;
    switch (t) { case 0: xp = x1; break; case 1: xp = x2; break;
                 case 2: xp = x3; break; default: xp = xf; }
    xp += (size_t)r * DD;

    float v[4]; float s = 0.f, q = 0.f;
    #pragma unroll
    for (int i = 0; i < 4; i++) {
        v[i] = xp[threadIdx.x + 256*i];
        s += v[i]; q += v[i]*v[i];
    }
    #pragma unroll
    for (int off = 16; off > 0; off >>= 1) {
        s += __shfl_down_sync(0xffffffffu, s, off);
        q += __shfl_down_sync(0xffffffffu, q, off);
    }
    __shared__ float sh1[8], sh2[8];
    if ((threadIdx.x & 31) == 0) { sh1[threadIdx.x >> 5] = s; sh2[threadIdx.x >> 5] = q; }
    __syncthreads();
    __shared__ float mu_s, rstd_s;
    if (threadIdx.x == 0) {
        float S = 0.f, Q = 0.f;
        #pragma unroll
        for (int i = 0; i < 8; i++) { S += sh1[i]; Q += sh2[i]; }
        float mu  = S / (float)DD;
        float var = Q / (float)DD - mu*mu;
        mu_s = mu; rstd_s = rsqrtf(var + 1e-6f);
    }
    __syncthreads();
    float mu = mu_s, rstd = rstd_s;
    const float* eo = g_eo[t][b];
    __half* hp = &g_h[(size_t)t*BTD + (size_t)r*DD];
    #pragma unroll
    for (int i = 0; i < 4; i++) {
        int d = threadIdx.x + 256*i;
        hp[d] = __float2half_rn((v[i] - mu) * rstd * (1.0f + eo[d]) + eo[DD + d]);
    }
}

// ---------------- batched FP16 GEMM: 4 warps x 64x64, K-major B, BK=64 ----------
// C[M,N] = A[M,K] @ W[K,N] + bias.  A smem [m][k] pitch 72h; B smem [k][n] pitch 136h.
#define HPA 72
#define HPB 136
#define HG_ABUF (128*HPA)                 // halves
#define HG_BBUF (64*HPB)                  // halves
#define HG_STAGE (HG_ABUF + HG_BBUF)      // 17920 halves = 35840 B
#define HG_SMEM_BYTES (2*HG_STAGE*2)      // 71680 B
#define MAXZ 5

struct GemmBatch {
    const __half* A[MAXZ];
    const __half* W[MAXZ];
    const float*  bias[MAXZ];
    float         bscale[MAXZ];
    void*         C[MAXZ];
};

__global__ void __launch_bounds__(128, 2)
hgemm(GemmBatch gb, int toHalf, int N, int K) {
    extern __shared__ __half hsm[];
    const uint32_t sbase = (uint32_t)__cvta_generic_to_shared(hsm);

    const int z = blockIdx.z;
    const __half* __restrict__ A  = gb.A[z];
    const __half* __restrict__ Wh = gb.W[z];
    const float* __restrict__ bias = gb.bias[z];
    const float bsc = gb.bscale[z];

    const int tid  = threadIdx.x;
    const int lane = tid & 31, warp = tid >> 5;
    const int g = lane >> 2, tig = lane & 3;
    const int mo = (warp >> 1) << 6;      // 0 / 64
    const int no = (warp & 1) << 6;       // 0 / 64
    const int brow = blockIdx.y << 7, bcol = blockIdx.x << 7;

    // A ldsm geometry (non-trans)
    const int lr  = lane & 7;
    const int rA  = lr + ((lane >> 3) & 1) * 8;
    const int khA = (lane >> 4) * 8;
    // B ldsm geometry (trans, like attention V)
    const int vr = (((lane >> 3) & 1) << 3) + (lane & 7);
    const int vc = (lane >> 4) << 3;

    float acc[4][8][4];
    #pragma unroll
    for (int mt = 0; mt < 4; mt++)
        #pragma unroll
        for (int nt = 0; nt < 8; nt++)
            #pragma unroll
            for (int i = 0; i < 4; i++) acc[mt][nt][i] = 0.f;

    auto stage = [&](int k0, int buf) {
        uint32_t oA = sbase + buf * (HG_STAGE*2);
        uint32_t oB = oA + HG_ABUF*2;
        #pragma unroll
        for (int j = 0; j < 8; j++) {      // A: 128 rows x 8 pieces (16B)
            int u = tid + j*128;
            int row = u >> 3, piece = u & 7;
            cp16(oA + row*(HPA*2) + piece*16, &A[(size_t)(brow + row)*K + k0 + piece*8]);
        }
        #pragma unroll
        for (int j = 0; j < 8; j++) {      // B: 64 k-rows x 16 pieces (128 cols)
            int u = tid + j*128;
            int row = u >> 4, piece = u & 15;
            cp16(oB + row*(HPB*2) + piece*16, &Wh[(size_t)(k0 + row)*N + bcol + piece*8]);
        }
        cp_commit();
    };

    stage(0, 0);

    const int iters = K >> 6;   // 16
    for (int it = 0; it < iters; ++it) {
        if (it + 1 < iters) {
            stage((it + 1) << 6, (it + 1) & 1);
            asm volatile("cp.async.wait_group 1;" ::: "memory");
        } else {
            asm volatile("cp.async.wait_group 0;" ::: "memory");
        }
        __syncthreads();

        const uint32_t aB = sbase + (it & 1) * (HG_STAGE*2);
        const uint32_t bB = aB + HG_ABUF*2;
        const uint32_t aAddr0 = aB + ((mo + rA)*HPA + khA)*2;
        const uint32_t bAddr0 = bB + (vr*HPB + no + vc)*2;

        #pragma unroll
        for (int ks = 0; ks < 4; ks++) {
            uint32_t afr[4][4], bfr[8][2];
            #pragma unroll
            for (int mt = 0; mt < 4; mt++)
                ldsm_x4(afr[mt][0], afr[mt][1], afr[mt][2], afr[mt][3],
                        aAddr0 + mt*(16*HPA*2) + ks*32);
            #pragma unroll
            for (int ng = 0; ng < 4; ng++)
                ldsm_x4_t(bfr[2*ng][0], bfr[2*ng][1], bfr[2*ng+1][0], bfr[2*ng+1][1],
                          bAddr0 + ks*(16*HPB*2) + ng*32);
            #pragma unroll
            for (int mt = 0; mt < 4; mt++)
                #pragma unroll
                for (int nt = 0; nt < 8; nt++)
                    mma_f16(acc[mt][nt], afr[mt][0], afr[mt][1], afr[mt][2], afr[mt][3],
                            bfr[nt][0], bfr[nt][1]);
        }
        __syncthreads();
    }

    if (toHalf) {
        __half* C = (__half*)gb.C[z];
        #pragma unroll
        for (int mt = 0; mt < 4; mt++) {
            int r0 = brow + mo + mt*16 + g;
            #pragma unroll
            for (int nt = 0; nt < 8; nt++) {
                int c = bcol + no + nt*8 + 2*tig;
                float b0 = bias[c]*bsc, b1 = bias[c + 1]*bsc;
                uint32_t h0 = packh2(acc[mt][nt][0] + b0, acc[mt][nt][1] + b1);
                uint32_t h1 = packh2(acc[mt][nt][2] + b0, acc[mt][nt][3] + b1);
                *(uint32_t*)&C[(size_t)r0       * N + c] = h0;
                *(uint32_t*)&C[(size_t)(r0 + 8) * N + c] = h1;
            }
        }
    } else {
        float* C = (float*)gb.C[z];
        #pragma unroll
        for (int mt = 0; mt < 4; mt++) {
            int r0 = brow + mo + mt*16 + g;
            #pragma unroll
            for (int nt = 0; nt < 8; nt++) {
                int c = bcol + no + nt*8 + 2*tig;
                float b0 = bias[c], b1 = bias[c + 1];
                *(float2*)&C[(size_t)r0       * N + c] =
                    make_float2(acc[mt][nt][0] + b0, acc[mt][nt][1] + b1);
                *(float2*)&C[(size_t)(r0 + 8) * N + c] =
                    make_float2(acc[mt][nt][2] + b0, acc[mt][nt][3] + b1);
            }
        }
    }
}

// ---------------- FP16 flash attention (round-8 version, unchanged) -------------
#define AQW   36
#define W_Q   0
#define W_K   4608
#define KWBUF 2304
#define W_V   9216
#define W_MS  13824
#define SMEM_ATTN_BYTES (W_MS*4 + 512)

__global__ void __launch_bounds__(256, 2)
attn_tc(const unsigned char* __restrict__ mask) {
    extern __shared__ uint32_t sw[];
    const uint32_t sbase = (uint32_t)__cvta_generic_to_shared(sw);

    const int br = blockIdx.z >> 2;
    const int b  = blockIdx.z & 3;
    const int h  = blockIdx.y;
    const int q0 = blockIdx.x << 7;

    const int tid  = threadIdx.x;
    const int lane = tid & 31, warp = tid >> 5;
    const int g = lane >> 2, tig = lane & 3;
    const int mo = warp << 4;

    const int lr  = lane & 7;
    const int rA  = lr + ((lane >> 3) & 1) * 8;
    const int khA = (lane >> 4) * 8;
    const int vr = (((lane >> 3) & 1) << 3) + (lane & 7);
    const int vc = (lane >> 4) << 3;

    const __half* Qg = &g_q[(size_t)br*BTD + ((size_t)(b*TT + q0))*DD + h*HD];
    const __half* Kg = &g_k[((size_t)(b*NKV))*DD + h*HD];
    const __half* Vg = &g_v[((size_t)(b*NKV))*DD + h*HD];

    #pragma unroll
    for (int j = 0; j < 4; j++) {
        int u = tid + j*256;
        int row = u >> 3, q = u & 7;
        cp16(sbase + W_Q*4 + row*144 + q*16, &Qg[(size_t)row*DD + q*8]);
    }
    if (tid < 32) cp16(sbase + W_MS*4 + tid*16, mask + b*NKV + tid*16);
    #pragma unroll
    for (int j = 0; j < 2; j++) {
        int u = tid + j*256;
        int row = u >> 3, q = u & 7;
        cp16(sbase + W_K*4 + row*144 + q*16, &Kg[(size_t)row*DD + q*8]);
        cp16(sbase + W_V*4 + row*144 + q*16, &Vg[(size_t)row*DD + q*8]);
    }
    if (tid < 64)   // V cols 64-71 = {1,0,...}
        *(uint4*)((char*)sw + W_V*4 + tid*144 + 128) = make_uint4(0x00003C00u, 0u, 0u, 0u);
    cp_commit();

    asm volatile("cp.async.wait_group 0;" ::: "memory");
    __syncthreads();

    uint32_t qa[4][4];
    {
        const uint32_t qAddr0 = sbase + W_Q*4 + (mo + rA)*144 + khA*2;
        #pragma unroll
        for (int ks = 0; ks < 4; ks++)
            ldsm_x4(qa[ks][0], qa[ks][1], qa[ks][2], qa[ks][3], qAddr0 + ks*32);
    }

    float o[9][4];
    #pragma unroll
    for (int nt = 0; nt < 9; nt++)
        #pragma unroll
        for (int i = 0; i < 4; i++) o[nt][i] = 0.f;
    float m0 = -1e30f, m1 = -1e30f;
    const float L2E = 1.4426950408889634f;

    for (int ci = 0; ci < 8; ci++) {
        const int kc = ci << 6;
        const int buf = ci & 1;
        if (ci < 7) {
            const int nb = buf ^ 1;
            #pragma unroll
            for (int j = 0; j < 2; j++) {
                int u = tid + j*256;
                int row = u >> 3, q = u & 7;
                size_t gsrc = (size_t)(kc + 64 + row)*DD + q*8;
                cp16(sbase + (W_K + nb*KWBUF)*4 + row*144 + q*16, &Kg[gsrc]);
                cp16(sbase + (W_V + nb*KWBUF)*4 + row*144 + q*16, &Vg[gsrc]);
            }
            if (tid < 64)
                *(uint4*)((char*)sw + (W_V + nb*KWBUF)*4 + tid*144 + 128) =
                    make_uint4(0x00003C00u, 0u, 0u, 0u);
            cp_commit();
            asm volatile("cp.async.wait_group 1;" ::: "memory");
        } else {
            asm volatile("cp.async.wait_group 0;" ::: "memory");
        }
        __syncthreads();

        const uint32_t kAddr0 = sbase + (W_K + buf*KWBUF)*4
                              + ((lane & 7) + ((lane >> 4) << 3))*144
                              + (((lane >> 3) & 1) * 8)*2;
        const unsigned char* ms = (const unsigned char*)(sw + W_MS) + kc;

        float s[8][4];
        #pragma unroll
        for (int nt = 0; nt < 8; nt++)
            #pragma unroll
            for (int i = 0; i < 4; i++) s[nt][i] = 0.f;

        #pragma unroll
        for (int ks = 0; ks < 4; ks++) {
            const int kh = ks*32;
            #pragma unroll
            for (int np = 0; np < 4; np++) {
                uint32_t b0, b1, b2, b3;
                ldsm_x4(b0, b1, b2, b3, kAddr0 + np*(16*144) + kh);
                mma_f16(s[2*np    ], qa[ks][0], qa[ks][1], qa[ks][2], qa[ks][3], b0, b1);
                mma_f16(s[2*np + 1], qa[ks][0], qa[ks][1], qa[ks][2], qa[ks][3], b2, b3);
            }
        }

        float rmax0 = -1e30f, rmax1 = -1e30f;
        #pragma unroll
        for (int nt = 0; nt < 8; nt++) {
            int c = nt*8 + 2*tig;
            if (ms[c    ]) { s[nt][0] = -1e30f; s[nt][2] = -1e30f; }
            if (ms[c + 1]) { s[nt][1] = -1e30f; s[nt][3] = -1e30f; }
            rmax0 = fmaxf(rmax0, fmaxf(s[nt][0], s[nt][1]));
            rmax1 = fmaxf(rmax1, fmaxf(s[nt][2], s[nt][3]));
        }
        #pragma unroll
        for (int off = 1; off <= 2; off <<= 1) {
            rmax0 = fmaxf(rmax0, __shfl_xor_sync(0xffffffffu, rmax0, off));
            rmax1 = fmaxf(rmax1, __shfl_xor_sync(0xffffffffu, rmax1, off));
        }
        float mn0 = fmaxf(m0, rmax0), mn1 = fmaxf(m1, rmax1);
        float f0 = __expf(m0 - mn0),  f1 = __expf(m1 - mn1);
        m0 = mn0; m1 = mn1;
        float nm0 = mn0 * L2E, nm1 = mn1 * L2E;

        uint32_t pA[8], pB[8];
        #pragma unroll
        for (int nt = 0; nt < 8; nt++) {
            float t0 = fmaf(s[nt][0], L2E, -nm0);
            float t1 = fmaf(s[nt][1], L2E, -nm0);
            float t2 = fmaf(s[nt][2], L2E, -nm1);
            float t3 = fmaf(s[nt][3], L2E, -nm1);
            pA[nt] = ex2h2(packh2(t0, t1));
            pB[nt] = ex2h2(packh2(t2, t3));
        }

        #pragma unroll
        for (int nt = 0; nt < 9; nt++) {
            o[nt][0] *= f0; o[nt][1] *= f0;
            o[nt][2] *= f1; o[nt][3] *= f1;
        }

        const uint32_t vwb4 = (W_V + buf*KWBUF)*4;
        #pragma unroll
        for (int kt = 0; kt < 4; kt++) {
            uint32_t a0 = pA[2*kt], a1 = pB[2*kt], a2 = pA[2*kt+1], a3 = pB[2*kt+1];
            #pragma unroll
            for (int np = 0; np < 4; np++) {
                uint32_t r0, r1, r2, r3;
                uint32_t addr = sbase + vwb4 + (kt*16 + vr)*144 + (np*16 + vc)*2;
                ldsm_x4_t(r0, r1, r2, r3, addr);
                mma_f16(o[2*np    ], a0, a1, a2, a3, r0, r1);
                mma_f16(o[2*np + 1], a0, a1, a2, a3, r2, r3);
            }
            {   // ones column block (cols 64-71)
                uint32_t r0, r1, r2, r3;
                uint32_t addr = sbase + vwb4 + (kt*16 + vr)*144 + (64 + vc)*2;
                ldsm_x4_t(r0, r1, r2, r3, addr);
                mma_f16(o[8], a0, a1, a2, a3, r0, r1);
            }
        }
        __syncthreads();
    }

    float lv0 = __shfl_sync(0xffffffffu, o[8][0], lane & ~3);
    float lv1 = __shfl_sync(0xffffffffu, o[8][2], lane & ~3);
    float rl0 = (lv0 > 0.f) ? 1.0f / lv0 : 0.f;
    float rl1 = (lv1 > 0.f) ? 1.0f / lv1 : 0.f;
    __half* Og = &g_ao[(size_t)br*BTD + ((size_t)(b*TT + q0))*DD + h*HD];
    #pragma unroll
    for (int nt = 0; nt < 8; nt++) {
        int c = nt*8 + 2*tig;
        uint32_t h0 = packh2(o[nt][0]*rl0, o[nt][1]*rl0);
        uint32_t h1 = packh2(o[nt][2]*rl1, o[nt][3]*rl1);
        *(uint32_t*)&Og[(size_t)(mo + g    )*DD + c] = h0;
        *(uint32_t*)&Og[(size_t)(mo + g + 8)*DD + c] = h1;
    }
}

// ---------------- launch ----------------
extern "C" void kernel_launch(void* const* d_in, const int* in_sizes, int n_in,
                              void* d_out, int out_size) {
    const float* x1        = (const float*)d_in[0];
    const float* x2        = (const float*)d_in[1];
    const float* x3        = (const float*)d_in[2];
    const float* xf        = (const float*)d_in[3];
    const float* emb       = (const float*)d_in[4];
    const unsigned char* mask = (const unsigned char*)d_in[5];
    const float* adaln_w   = (const float*)d_in[6];
    const float* adaln_b   = (const float*)d_in[7];
    const float* xf_adaln_w= (const float*)d_in[8];
    const float* xf_adaln_b= (const float*)d_in[9];
    const float* q_w       = (const float*)d_in[10];
    const float* q_b       = (const float*)d_in[11];
    const float* k_w       = (const float*)d_in[12];
    const float* k_b       = (const float*)d_in[13];
    const float* v_w       = (const float*)d_in[14];
    const float* v_b       = (const float*)d_in[15];
    const float* out_w     = (const float*)d_in[16];
    const float* out_b     = (const float*)d_in[17];
    float* out = (float*)d_out;

    __half *hP, *qP, *kP, *vP, *aoP, *wrP;
    cudaGetSymbolAddress((void**)&hP,  g_h);
    cudaGetSymbolAddress((void**)&qP,  g_q);
    cudaGetSymbolAddress((void**)&kP,  g_k);
    cudaGetSymbolAddress((void**)&vP,  g_v);
    cudaGetSymbolAddress((void**)&aoP, g_ao);
    cudaGetSymbolAddress((void**)&wrP, g_wr);

    static bool attr_set = false;
    if (!attr_set) {
        cudaFuncSetAttribute(attn_tc, cudaFuncAttributeMaxDynamicSharedMemorySize,
                             SMEM_ATTN_BYTES);
        cudaFuncSetAttribute(hgemm, cudaFuncAttributeMaxDynamicSharedMemorySize,
                             HG_SMEM_BYTES);
        attr_set = true;
    }

    prep_w<<<4096, 256>>>(q_w, k_w, v_w, out_w);
    adaln_k<<<64, 256>>>(emb, adaln_w, adaln_b, xf_adaln_w, xf_adaln_b);
    ln_mod_k<<<4 * BB * TT, 256>>>(x1, x2, x3, xf);

    // batched QKV projections: z = {Q0,Q1,Q2,K,V}; fp16 outputs; Q bias scaled 1/8
    GemmBatch gq;
    for (int i = 0; i < 3; i++) {
        gq.A[i] = hP + (size_t)i*BTD; gq.W[i] = wrP + (size_t)i*DD*DD;
        gq.bias[i] = q_b + i*DD;      gq.C[i] = qP + (size_t)i*BTD;
        gq.bscale[i] = 0.125f;
    }
    gq.A[3] = hP + (size_t)3*BTD; gq.W[3] = wrP + (size_t)3*DD*DD; gq.bias[3] = k_b; gq.C[3] = kP; gq.bscale[3] = 1.0f;
    gq.A[4] = hP + (size_t)3*BTD; gq.W[4] = wrP + (size_t)4*DD*DD; gq.bias[4] = v_b; gq.C[4] = vP; gq.bscale[4] = 1.0f;
    hgemm<<<dim3(DD/128, (BB*TT)/128, 5), 128, HG_SMEM_BYTES>>>(gq, 1, DD, DD);

    attn_tc<<<dim3(TT/128, HH, 3*BB), 256, SMEM_ATTN_BYTES>>>(mask);

    // batched output projections, fp32 outputs
    GemmBatch go;
    for (int i = 0; i < 3; i++) {
        go.A[i] = aoP + (size_t)i*BTD; go.W[i] = wrP + (size_t)(5 + i)*DD*DD;
        go.bias[i] = out_b + i*DD;     go.C[i] = out + (size_t)i*BTD;
        go.bscale[i] = 1.0f;
    }
    for (int i = 3; i < MAXZ; i++) { go.A[i] = nullptr; go.W[i] = nullptr; go.bias[i] = nullptr; go.C[i] = nullptr; go.bscale[i] = 1.0f; }
    hgemm<<<dim3(DD/128, (BB*TT)/128, 3), 128, HG_SMEM_BYTES>>>(go, 0, DD, DD);
}